// round 9
// baseline (speedup 1.0000x reference)
#include <cuda_runtime.h>
#include <math.h>
#include <stdint.h>

// Problem constants
constexpr int Bb   = 8;
constexpr int T    = 1024;
constexpr int Dm   = 1024;
constexpr int NH   = 16;
constexpr int HD   = 64;
constexpr int FF   = 4096;
constexpr int MTOK = Bb * T;            // 8192 tokens

// ----------------------------------------------------------------------------
// Scratch (allocation-free: __device__ globals)
// ----------------------------------------------------------------------------
__device__ __align__(256) float g_xn[(size_t)MTOK * Dm];
__device__ __align__(256) float g_q [(size_t)MTOK * Dm];
__device__ __align__(256) float g_k [(size_t)MTOK * Dm];
__device__ __align__(256) float g_v [(size_t)MTOK * Dm];
__device__ __align__(256) float g_sc[(size_t)Bb * NH * T * T];   // 512 MB scores
__device__ __align__(256) float g_ao[(size_t)MTOK * Dm];
__device__ __align__(256) float g_at[(size_t)MTOK * Dm];
__device__ __align__(256) float g_ln[(size_t)MTOK * Dm];
__device__ __align__(256) float g_h1[(size_t)MTOK * FF];
// tf32-rounded weight copies
__device__ __align__(256) float g_wqR[(size_t)Dm * Dm];
__device__ __align__(256) float g_wkR[(size_t)Dm * Dm];
__device__ __align__(256) float g_wvR[(size_t)Dm * Dm];
__device__ __align__(256) float g_woR[(size_t)Dm * Dm];
__device__ __align__(256) float g_w1R[(size_t)Dm * FF];
__device__ __align__(256) float g_w2R[(size_t)FF * Dm];

// ----------------------------------------------------------------------------
// Baseline-PTX helpers (no 'a'-gated instructions — harness compiles compute_103)
// ----------------------------------------------------------------------------
__device__ __forceinline__ uint32_t smem_u32(const void* p) {
    uint32_t a;
    asm("{ .reg .u64 t; cvta.to.shared.u64 t, %1; cvt.u32.u64 %0, t; }" : "=r"(a) : "l"(p));
    return a;
}
__device__ __forceinline__ void cpa16(void* dst, const void* src) {
    uint32_t d = smem_u32(dst);
    asm volatile("cp.async.cg.shared.global [%0], [%1], 16;" :: "r"(d), "l"(src) : "memory");
}
// All GEMM operands are pre-rounded to tf32 (RNA) by producers, so raw-bit
// truncation here is lossless — no cvt in the inner loop.
__device__ __forceinline__ uint32_t f2tf(float f) {
    return __float_as_uint(f);
}
// RNA tf32 rounding (used in producer epilogues only)
__device__ __forceinline__ float rndtf(float f) {
    uint32_t u;
    asm("cvt.rna.tf32.f32 %0, %1;" : "=r"(u) : "f"(f));
    return __uint_as_float(u);
}
__device__ __forceinline__ void mma8(float* c, const uint32_t* a, uint32_t b0, uint32_t b1) {
    asm volatile(
        "mma.sync.aligned.m16n8k8.row.col.f32.tf32.tf32.f32 "
        "{%0,%1,%2,%3}, {%4,%5,%6,%7}, {%8,%9}, {%0,%1,%2,%3};"
        : "+f"(c[0]), "+f"(c[1]), "+f"(c[2]), "+f"(c[3])
        : "r"(a[0]), "r"(a[1]), "r"(a[2]), "r"(a[3]), "r"(b0), "r"(b1));
}

// ----------------------------------------------------------------------------
// Big-tile GEMM: 128x128 CTA, 128 threads = 4 warps of 64x64 (LDS:HMMA = 1:1),
// K slab 32, double-buffered cp.async, 2 CTAs/SM.
// A row-major. B: TB=false -> B[k][n]; TB=true -> B[n][k].
// Epilogue: +bias, *softplus-q-scale, ReLU, +resid, tf32-round (rnd).
// ----------------------------------------------------------------------------
template <int BN, bool TB>
__global__ void __launch_bounds__(128, 2) gemm_big(
    const float* __restrict__ A, const float* __restrict__ B, float* __restrict__ C,
    int K, int lda, int ldb, int ldc, int zdiv,
    long long sA1, long long sA2, long long sB1, long long sB2,
    long long sC1, long long sC2,
    const float* __restrict__ bias, const float* __restrict__ resid,
    const float* __restrict__ pds, int relu, int causal, int rnd)
{
    constexpr int BMb = 128, BKb = 32;
    constexpr int AW = BKb + 4;
    constexpr int BW = TB ? (BKb + 4) : (BN + 8);
    constexpr int AS = BMb * AW;
    constexpr int BS = TB ? BN * BW : BKb * BW;
    constexpr int STW = AS + BS;
    constexpr int NT = BN / 16;                 // warp col tile = BN/2, 8-wide subtiles
    extern __shared__ float sm[];

    int m0 = blockIdx.y * BMb;
    int n0 = blockIdx.x * BN;
    if (causal && n0 > m0 + BMb - 1) return;

    int z = blockIdx.z, z1 = z / zdiv, z2 = z - z1 * zdiv;
    A += z1 * sA1 + z2 * sA2;
    B += z1 * sB1 + z2 * sB2;
    long long oC = z1 * sC1 + z2 * sC2;

    int tid  = threadIdx.x;
    int lane = tid & 31;
    int w    = tid >> 5;
    int g    = lane >> 2, tg = lane & 3;
    int wrow = (w >> 1) * 64;
    int wcol = (w & 1) * (BN / 2);

    float acc[4][NT][4];
    #pragma unroll
    for (int mt = 0; mt < 4; mt++)
        #pragma unroll
        for (int nt = 0; nt < NT; nt++)
            #pragma unroll
            for (int i = 0; i < 4; i++) acc[mt][nt][i] = 0.f;

    int nslab = K / BKb;

    auto loadSlab = [&](int buf, int slab) {
        float* As = sm + buf * STW;
        float* Bs = As + AS;
        int ko = slab * BKb;
        #pragma unroll
        for (int i = 0; i < 8; i++) {                       // A: 128 x 8 float4
            int c = tid + i * 128;
            int r = c >> 3, f = (c & 7) * 4;
            cpa16(&As[r * AW + f], A + (long long)(m0 + r) * lda + ko + f);
        }
        if (TB) {
            #pragma unroll
            for (int i = 0; i < BN / 16; i++) {             // B: BN x 8 float4
                int c = tid + i * 128;
                int r = c >> 3, f = (c & 7) * 4;
                cpa16(&Bs[r * BW + f], B + (long long)(n0 + r) * ldb + ko + f);
            }
        } else {
            #pragma unroll
            for (int i = 0; i < BN / 16; i++) {             // B: 32 x (BN/4) float4
                int c = tid + i * 128;
                int r = c / (BN / 4), f = (c % (BN / 4)) * 4;
                cpa16(&Bs[r * BW + f], B + (long long)(ko + r) * ldb + n0 + f);
            }
        }
        asm volatile("cp.async.commit_group;" ::: "memory");
    };

    auto compute = [&](int buf) {
        const float* As = sm + buf * STW;
        const float* Bs = As + AS;
        #pragma unroll
        for (int kk = 0; kk < 4; kk++) {
            int k = kk * 8;
            uint32_t af[4][4];
            #pragma unroll
            for (int mt = 0; mt < 4; mt++) {
                int r = wrow + mt * 16 + g;
                af[mt][0] = f2tf(As[r * AW + k + tg]);
                af[mt][1] = f2tf(As[(r + 8) * AW + k + tg]);
                af[mt][2] = f2tf(As[r * AW + k + tg + 4]);
                af[mt][3] = f2tf(As[(r + 8) * AW + k + tg + 4]);
            }
            #pragma unroll
            for (int nt = 0; nt < NT; nt++) {
                int cn = wcol + nt * 8 + g;
                uint32_t b0, b1;
                if (TB) {
                    b0 = f2tf(Bs[cn * BW + k + tg]);
                    b1 = f2tf(Bs[cn * BW + k + tg + 4]);
                } else {
                    b0 = f2tf(Bs[(k + tg) * BW + cn]);
                    b1 = f2tf(Bs[(k + tg + 4) * BW + cn]);
                }
                #pragma unroll
                for (int mt = 0; mt < 4; mt++)
                    mma8(acc[mt][nt], af[mt], b0, b1);
            }
        }
    };

    loadSlab(0, 0);
    for (int s = 0; s < nslab; s++) {
        if (s + 1 < nslab) {
            loadSlab((s + 1) & 1, s + 1);
            asm volatile("cp.async.wait_group 1;" ::: "memory");
        } else {
            asm volatile("cp.async.wait_group 0;" ::: "memory");
        }
        __syncthreads();
        compute(s & 1);
        __syncthreads();
    }

    // Epilogue
    float* Cb = C + oC;
    const float* Rb = resid ? resid + oC : nullptr;
    #pragma unroll
    for (int mt = 0; mt < 4; mt++) {
        #pragma unroll
        for (int nt = 0; nt < NT; nt++) {
            int cn = n0 + wcol + nt * 8 + 2 * tg;
            float bv0 = 0.f, bv1 = 0.f, s0 = 1.f, s1 = 1.f;
            if (bias) { bv0 = bias[cn]; bv1 = bias[cn + 1]; }
            if (pds) {
                float p0 = pds[cn & (HD - 1)], p1 = pds[(cn + 1) & (HD - 1)];
                float sp0 = (p0 > 20.f) ? p0 : log1pf(expf(p0));
                float sp1 = (p1 > 20.f) ? p1 : log1pf(expf(p1));
                s0 = 0.1803368801111f * sp0;   // log2(e)/sqrt(64) * softplus
                s1 = 0.1803368801111f * sp1;
            }
            #pragma unroll
            for (int h = 0; h < 2; h++) {
                int r = m0 + wrow + mt * 16 + g + h * 8;
                float v0 = acc[mt][nt][h * 2 + 0];
                float v1 = acc[mt][nt][h * 2 + 1];
                if (bias) { v0 += bv0; v1 += bv1; }
                if (pds)  { v0 *= s0; v1 *= s1; }
                if (relu) { v0 = fmaxf(v0, 0.f); v1 = fmaxf(v1, 0.f); }
                long long off = (long long)r * ldc + cn;
                if (Rb) {
                    float2 rr = *reinterpret_cast<const float2*>(Rb + off);
                    v0 += rr.x; v1 += rr.y;
                }
                if (rnd) { v0 = rndtf(v0); v1 = rndtf(v1); }
                *reinterpret_cast<float2*>(Cb + off) = make_float2(v0, v1);
            }
        }
    }
}

// ----------------------------------------------------------------------------
// PV GEMM (N=64): proven 256-thread kernel, 2 CTAs/SM, causal-K clamp.
// ----------------------------------------------------------------------------
constexpr int BM = 128;
constexpr int BK = 32;

template <int BN, bool TB>
__global__ void __launch_bounds__(256, 2) gemm_mma(
    const float* __restrict__ A, const float* __restrict__ B, float* __restrict__ C,
    int K, int lda, int ldb, int ldc, int zdiv,
    long long sA1, long long sA2, long long sB1, long long sB2,
    long long sC1, long long sC2,
    const float* __restrict__ bias, const float* __restrict__ resid,
    const float* __restrict__ pds, int relu, int causal, int causalK, int rnd)
{
    constexpr int AW = BK + 4;
    constexpr int BW = TB ? (BK + 4) : (BN + 8);
    constexpr int AS = BM * AW;
    constexpr int BS = TB ? BN * BW : BK * BW;
    constexpr int STW = AS + BS;
    constexpr int NT = BN / 16;
    extern __shared__ float sm[];

    int m0 = blockIdx.y * BM;
    int n0 = blockIdx.x * BN;
    if (causal && n0 > m0 + BM - 1) return;

    int z = blockIdx.z, z1 = z / zdiv, z2 = z - z1 * zdiv;
    A += z1 * sA1 + z2 * sA2;
    B += z1 * sB1 + z2 * sB2;
    long long oC = z1 * sC1 + z2 * sC2;

    int tid  = threadIdx.x;
    int lane = tid & 31;
    int w    = tid >> 5;
    int g    = lane >> 2, tg = lane & 3;
    int wm   = (w & 3) * 32;
    int wn   = (w >> 2) * (BN / 2);

    float acc[2][NT][4];
    #pragma unroll
    for (int mt = 0; mt < 2; mt++)
        #pragma unroll
        for (int nt = 0; nt < NT; nt++)
            #pragma unroll
            for (int i = 0; i < 4; i++) acc[mt][nt][i] = 0.f;

    int Keff = K;
    if (causalK && m0 + BM < K) Keff = m0 + BM;   // P[t][s] == 0 for s > t
    int nslab = Keff / BK;

    auto loadSlab = [&](int buf, int slab) {
        float* As = sm + buf * STW;
        float* Bs = As + AS;
        int ko = slab * BK;
        #pragma unroll
        for (int i = 0; i < (BM * 8) / 256; i++) {
            int c = tid + i * 256;
            int r = c >> 3, f = (c & 7) * 4;
            cpa16(&As[r * AW + f], A + (long long)(m0 + r) * lda + ko + f);
        }
        if (TB) {
            #pragma unroll
            for (int i = 0; i < (BN * 8) / 256; i++) {
                int c = tid + i * 256;
                int r = c >> 3, f = (c & 7) * 4;
                cpa16(&Bs[r * BW + f], B + (long long)(n0 + r) * ldb + ko + f);
            }
        } else {
            #pragma unroll
            for (int i = 0; i < (BK * (BN / 4)) / 256; i++) {
                int c = tid + i * 256;
                int r = c / (BN / 4), f = (c % (BN / 4)) * 4;
                cpa16(&Bs[r * BW + f], B + (long long)(ko + r) * ldb + n0 + f);
            }
        }
        asm volatile("cp.async.commit_group;" ::: "memory");
    };

    auto compute = [&](int buf) {
        const float* As = sm + buf * STW;
        const float* Bs = As + AS;
        #pragma unroll
        for (int kk = 0; kk < 4; kk++) {
            int k = kk * 8;
            uint32_t af[2][4];
            #pragma unroll
            for (int mt = 0; mt < 2; mt++) {
                int r = wm + mt * 16 + g;
                af[mt][0] = f2tf(As[r * AW + k + tg]);
                af[mt][1] = f2tf(As[(r + 8) * AW + k + tg]);
                af[mt][2] = f2tf(As[r * AW + k + tg + 4]);
                af[mt][3] = f2tf(As[(r + 8) * AW + k + tg + 4]);
            }
            #pragma unroll
            for (int nt = 0; nt < NT; nt++) {
                int cn = wn + nt * 8 + g;
                uint32_t b0, b1;
                if (TB) {
                    b0 = f2tf(Bs[cn * BW + k + tg]);
                    b1 = f2tf(Bs[cn * BW + k + tg + 4]);
                } else {
                    b0 = f2tf(Bs[(k + tg) * BW + cn]);
                    b1 = f2tf(Bs[(k + tg + 4) * BW + cn]);
                }
                #pragma unroll
                for (int mt = 0; mt < 2; mt++)
                    mma8(acc[mt][nt], af[mt], b0, b1);
            }
        }
    };

    loadSlab(0, 0);
    for (int s = 0; s < nslab; s++) {
        if (s + 1 < nslab) {
            loadSlab((s + 1) & 1, s + 1);
            asm volatile("cp.async.wait_group 1;" ::: "memory");
        } else {
            asm volatile("cp.async.wait_group 0;" ::: "memory");
        }
        __syncthreads();
        compute(s & 1);
        __syncthreads();
    }

    float* Cb = C + oC;
    const float* Rb = resid ? resid + oC : nullptr;
    #pragma unroll
    for (int mt = 0; mt < 2; mt++) {
        #pragma unroll
        for (int nt = 0; nt < NT; nt++) {
            int cn = n0 + wn + nt * 8 + 2 * tg;
            float bv0 = 0.f, bv1 = 0.f;
            if (bias) { bv0 = bias[cn]; bv1 = bias[cn + 1]; }
            #pragma unroll
            for (int h = 0; h < 2; h++) {
                int r = m0 + wm + mt * 16 + g + h * 8;
                float v0 = acc[mt][nt][h * 2 + 0];
                float v1 = acc[mt][nt][h * 2 + 1];
                if (bias) { v0 += bv0; v1 += bv1; }
                if (relu) { v0 = fmaxf(v0, 0.f); v1 = fmaxf(v1, 0.f); }
                long long off = (long long)r * ldc + cn;
                if (Rb) {
                    float2 rr = *reinterpret_cast<const float2*>(Rb + off);
                    v0 += rr.x; v1 += rr.y;
                }
                if (rnd) { v0 = rndtf(v0); v1 = rndtf(v1); }
                *reinterpret_cast<float2*>(Cb + off) = make_float2(v0, v1);
            }
        }
    }
}

// ----------------------------------------------------------------------------
// Elementwise kernels
// ----------------------------------------------------------------------------
__device__ __forceinline__ float warpSum(float v) {
    #pragma unroll
    for (int o = 16; o > 0; o >>= 1) v += __shfl_xor_sync(0xffffffffu, v, o);
    return v;
}
__device__ __forceinline__ float warpMax(float v) {
    #pragma unroll
    for (int o = 16; o > 0; o >>= 1) v = fmaxf(v, __shfl_xor_sync(0xffffffffu, v, o));
    return v;
}

// tf32-round copy (weights)
__global__ void __launch_bounds__(256) roundcp_k(const float4* __restrict__ in,
                                                 float4* __restrict__ out, int n4) {
    int i = blockIdx.x * 256 + threadIdx.x;
    if (i < n4) {
        float4 v = in[i];
        v.x = rndtf(v.x); v.y = rndtf(v.y); v.z = rndtf(v.z); v.w = rndtf(v.w);
        out[i] = v;
    }
}

__global__ void __launch_bounds__(256) rmsnorm_k(const float* __restrict__ x,
                                                 const float* __restrict__ g,
                                                 float* __restrict__ out) {
    size_t base = (size_t)blockIdx.x * Dm;
    int tid = threadIdx.x;
    float4 xv = reinterpret_cast<const float4*>(x + base)[tid];
    float ss = xv.x * xv.x + xv.y * xv.y + xv.z * xv.z + xv.w * xv.w;
    __shared__ float sh[8];
    __shared__ float bval;
    ss = warpSum(ss);
    if ((tid & 31) == 0) sh[tid >> 5] = ss;
    __syncthreads();
    if (tid == 0) {
        float s = 0.f;
        #pragma unroll
        for (int i = 0; i < 8; i++) s += sh[i];
        bval = s;
    }
    __syncthreads();
    float r = rsqrtf(bval * (1.0f / Dm) + 1e-6f);
    float4 gv = reinterpret_cast<const float4*>(g)[tid];
    reinterpret_cast<float4*>(out + base)[tid] =
        make_float4(rndtf(xv.x * r * gv.x), rndtf(xv.y * r * gv.y),
                    rndtf(xv.z * r * gv.z), rndtf(xv.w * r * gv.w));
}

__global__ void __launch_bounds__(256) layernorm_k(const float* __restrict__ x,
                                                   const float* __restrict__ gamma,
                                                   const float* __restrict__ beta,
                                                   float* __restrict__ out) {
    size_t base = (size_t)blockIdx.x * Dm;
    int tid = threadIdx.x;
    float4 xv = reinterpret_cast<const float4*>(x + base)[tid];
    float s1 = xv.x + xv.y + xv.z + xv.w;
    float s2 = xv.x * xv.x + xv.y * xv.y + xv.z * xv.z + xv.w * xv.w;
    __shared__ float shA[8], shB[8];
    __shared__ float bm, bv2;
    s1 = warpSum(s1);
    s2 = warpSum(s2);
    if ((tid & 31) == 0) { shA[tid >> 5] = s1; shB[tid >> 5] = s2; }
    __syncthreads();
    if (tid == 0) {
        float a = 0.f, b = 0.f;
        #pragma unroll
        for (int i = 0; i < 8; i++) { a += shA[i]; b += shB[i]; }
        bm = a * (1.0f / Dm); bv2 = b * (1.0f / Dm);
    }
    __syncthreads();
    float mean = bm;
    float r = rsqrtf(bv2 - mean * mean + 1e-5f);
    float4 gv = reinterpret_cast<const float4*>(gamma)[tid];
    float4 bvv = reinterpret_cast<const float4*>(beta)[tid];
    reinterpret_cast<float4*>(out + base)[tid] =
        make_float4(rndtf((xv.x - mean) * r * gv.x + bvv.x),
                    rndtf((xv.y - mean) * r * gv.y + bvv.y),
                    rndtf((xv.z - mean) * r * gv.z + bvv.z),
                    rndtf((xv.w - mean) * r * gv.w + bvv.w));
}

// Masked softmax, causal-limited: only s < L = roundup128(t+1) is ever read
// downstream (PV clamps K to the diagonal tile), and scores beyond L were
// never written. Output rounded to tf32 (PV operand).
__global__ void __launch_bounds__(256) softmax_k(float* __restrict__ sc,
                                                 const float* __restrict__ padding) {
    int t = blockIdx.x;
    int z = blockIdx.y;
    int b = z >> 4;
    int L = ((t >> 7) + 1) << 7;              // tile-rounded causal length
    float* row = sc + ((size_t)z * T + t) * T;
    int tid = threadIdx.x;
    int s0 = tid * 4;
    bool act = s0 < L;

    float vals[4] = {-1e9f, -1e9f, -1e9f, -1e9f};
    if (act) {
        float4 rv = reinterpret_cast<float4*>(row)[tid];
        float4 pv = reinterpret_cast<const float4*>(padding + (size_t)b * T)[tid];
        float padt = padding[(size_t)b * T + t];
        float vv[4] = {rv.x, rv.y, rv.z, rv.w};
        float pp[4] = {pv.x, pv.y, pv.z, pv.w};
        #pragma unroll
        for (int i = 0; i < 4; i++) {
            bool ok = (s0 + i <= t) && (padt != 0.f) && (pp[i] != 0.f);
            vals[i] = ok ? vv[i] : -1e9f;
        }
    }
    float mx = fmaxf(fmaxf(vals[0], vals[1]), fmaxf(vals[2], vals[3]));

    __shared__ float sh[8];
    __shared__ float bmax, bsum;
    mx = warpMax(mx);
    if ((tid & 31) == 0) sh[tid >> 5] = mx;
    __syncthreads();
    if (tid == 0) {
        float m = sh[0];
        #pragma unroll
        for (int i = 1; i < 8; i++) m = fmaxf(m, sh[i]);
        bmax = m;
    }
    __syncthreads();
    mx = bmax;
    float e[4], ls = 0.f;
    #pragma unroll
    for (int i = 0; i < 4; i++) { e[i] = __expf(vals[i] - mx); ls += e[i]; }
    ls = warpSum(ls);
    if ((tid & 31) == 0) sh[tid >> 5] = ls;
    __syncthreads();
    if (tid == 0) {
        float s = 0.f;
        #pragma unroll
        for (int i = 0; i < 8; i++) s += sh[i];
        bsum = s;
    }
    __syncthreads();
    float inv = 1.0f / bsum;
    if (act) {
        reinterpret_cast<float4*>(row)[tid] =
            make_float4(rndtf(e[0] * inv), rndtf(e[1] * inv),
                        rndtf(e[2] * inv), rndtf(e[3] * inv));
    }
}

// ----------------------------------------------------------------------------
// Launch
// ----------------------------------------------------------------------------
extern "C" void kernel_launch(void* const* d_in, const int* in_sizes, int n_in,
                              void* d_out, int out_size) {
    const float* x    = (const float*)d_in[0];
    const float* pad  = (const float*)d_in[1];
    const float* rmss = (const float*)d_in[2];
    const float* pds  = (const float*)d_in[3];
    const float* wq   = (const float*)d_in[4];
    const float* bq   = (const float*)d_in[5];
    const float* wk   = (const float*)d_in[6];
    const float* bk   = (const float*)d_in[7];
    const float* wv   = (const float*)d_in[8];
    const float* bv   = (const float*)d_in[9];
    const float* wo   = (const float*)d_in[10];
    const float* bo   = (const float*)d_in[11];
    const float* lng  = (const float*)d_in[12];
    const float* lnb  = (const float*)d_in[13];
    const float* w1   = (const float*)d_in[14];
    const float* b1   = (const float*)d_in[15];
    const float* w2   = (const float*)d_in[16];
    const float* b2   = (const float*)d_in[17];
    float* out = (float*)d_out;

    float *xn, *q, *k, *v, *sc, *ao, *at, *ln, *h1;
    float *wqR, *wkR, *wvR, *woR, *w1R, *w2R;
    cudaGetSymbolAddress((void**)&xn, g_xn);
    cudaGetSymbolAddress((void**)&q,  g_q);
    cudaGetSymbolAddress((void**)&k,  g_k);
    cudaGetSymbolAddress((void**)&v,  g_v);
    cudaGetSymbolAddress((void**)&sc, g_sc);
    cudaGetSymbolAddress((void**)&ao, g_ao);
    cudaGetSymbolAddress((void**)&at, g_at);
    cudaGetSymbolAddress((void**)&ln, g_ln);
    cudaGetSymbolAddress((void**)&h1, g_h1);
    cudaGetSymbolAddress((void**)&wqR, g_wqR);
    cudaGetSymbolAddress((void**)&wkR, g_wkR);
    cudaGetSymbolAddress((void**)&wvR, g_wvR);
    cudaGetSymbolAddress((void**)&woR, g_woR);
    cudaGetSymbolAddress((void**)&w1R, g_w1R);
    cudaGetSymbolAddress((void**)&w2R, g_w2R);

    // Dynamic smem (bytes)
    const int SMB_F = (128 * 36 + 32 * 136) * 2 * 4;   // gemm_big<128,false>: 71680
    const int SMB_T = (128 * 36 + 128 * 36) * 2 * 4;   // gemm_big<128,true> : 73728
    const int SMF64 = (128 * 36 + 32 * 72) * 2 * 4;    // gemm_mma<64,false> : 55296
    cudaFuncSetAttribute(gemm_big<128, false>, cudaFuncAttributeMaxDynamicSharedMemorySize, SMB_F);
    cudaFuncSetAttribute(gemm_big<128, true>,  cudaFuncAttributeMaxDynamicSharedMemorySize, SMB_T);
    cudaFuncSetAttribute(gemm_mma<64,  false>, cudaFuncAttributeMaxDynamicSharedMemorySize, SMF64);

    const long long Z = 0;

    // 0. tf32-rounded weight copies (one-time per launch, ~25us)
    roundcp_k<<<1024, 256>>>((const float4*)wq, (float4*)wqR, Dm * Dm / 4);
    roundcp_k<<<1024, 256>>>((const float4*)wk, (float4*)wkR, Dm * Dm / 4);
    roundcp_k<<<1024, 256>>>((const float4*)wv, (float4*)wvR, Dm * Dm / 4);
    roundcp_k<<<1024, 256>>>((const float4*)wo, (float4*)woR, Dm * Dm / 4);
    roundcp_k<<<4096, 256>>>((const float4*)w1, (float4*)w1R, Dm * FF / 4);
    roundcp_k<<<4096, 256>>>((const float4*)w2, (float4*)w2R, FF * Dm / 4);

    // 1. RMSNorm (tf32-rounded output)
    rmsnorm_k<<<MTOK, 256>>>(x, rmss, xn);

    // 2. Q/K/V projections (rounded outputs; Q fuses bias + softplus scale)
    gemm_big<128, false><<<dim3(Dm / 128, MTOK / 128, 1), 128, SMB_F>>>(
        xn, wqR, q, Dm, Dm, Dm, Dm, 1, Z, Z, Z, Z, Z, Z, bq, nullptr, pds, 0, 0, 1);
    gemm_big<128, false><<<dim3(Dm / 128, MTOK / 128, 1), 128, SMB_F>>>(
        xn, wkR, k, Dm, Dm, Dm, Dm, 1, Z, Z, Z, Z, Z, Z, bk, nullptr, nullptr, 0, 0, 1);
    gemm_big<128, false><<<dim3(Dm / 128, MTOK / 128, 1), 128, SMB_F>>>(
        xn, wvR, v, Dm, Dm, Dm, Dm, 1, Z, Z, Z, Z, Z, Z, bv, nullptr, nullptr, 0, 0, 1);

    // 3. scores[b,n,t,s] = Q K^T (batched over b,n; causal tile skip)
    gemm_big<128, true><<<dim3(T / 128, T / 128, Bb * NH), 128, SMB_T>>>(
        q, k, sc, HD, Dm, Dm, T, NH,
        (long long)T * Dm, (long long)HD,
        (long long)T * Dm, (long long)HD,
        (long long)NH * T * T, (long long)T * T,
        nullptr, nullptr, nullptr, 0, 1, 0);

    // 4. masked softmax (causal-limited, rounded output)
    softmax_k<<<dim3(T, Bb * NH), 256>>>(sc, pad);

    // 5. attn_out[b,t,n,h] = P V (K clamped to diagonal; rounded output)
    gemm_mma<64, false><<<dim3(1, T / 128, Bb * NH), 256, SMF64>>>(
        sc, v, ao, T, T, Dm, Dm, NH,
        (long long)NH * T * T, (long long)T * T,
        (long long)T * Dm, (long long)HD,
        (long long)T * Dm, (long long)HD,
        nullptr, nullptr, nullptr, 0, 0, 1, 1);

    // 6. out-proj + bo + residual(x)  (exact fp32 output)
    gemm_big<128, true><<<dim3(Dm / 128, MTOK / 128, 1), 128, SMB_T>>>(
        ao, woR, at, Dm, Dm, Dm, Dm, 1, Z, Z, Z, Z, Z, Z, bo, x, nullptr, 0, 0, 0);

    // 7. LayerNorm (rounded output)
    layernorm_k<<<MTOK, 256>>>(at, lng, lnb, ln);

    // 8. FFN1 + ReLU (rounded output)
    gemm_big<128, false><<<dim3(FF / 128, MTOK / 128, 1), 128, SMB_F>>>(
        ln, w1R, h1, Dm, Dm, FF, FF, 1, Z, Z, Z, Z, Z, Z, b1, nullptr, nullptr, 1, 0, 1);

    // 9. FFN2 + b2 + residual(at) -> out (exact fp32 output)
    gemm_big<128, false><<<dim3(Dm / 128, MTOK / 128, 1), 128, SMB_F>>>(
        h1, w2R, out, FF, FF, Dm, Dm, 1, Z, Z, Z, Z, Z, Z, b2, at, nullptr, 0, 0, 0);
}

// round 11
// speedup vs baseline: 1.0527x; 1.0527x over previous
#include <cuda_runtime.h>
#include <math.h>
#include <stdint.h>

// Problem constants
constexpr int Bb   = 8;
constexpr int T    = 1024;
constexpr int Dm   = 1024;
constexpr int NH   = 16;
constexpr int HD   = 64;
constexpr int FF   = 4096;
constexpr int MTOK = Bb * T;            // 8192 tokens

// ----------------------------------------------------------------------------
// Scratch (allocation-free: __device__ globals)
// ----------------------------------------------------------------------------
__device__ __align__(256) float g_xn[(size_t)MTOK * Dm];
__device__ __align__(256) float g_q [(size_t)MTOK * Dm];
__device__ __align__(256) float g_k [(size_t)MTOK * Dm];
__device__ __align__(256) float g_v [(size_t)MTOK * Dm];
__device__ __align__(256) float g_sc[(size_t)Bb * NH * T * T];   // 512 MB scores
__device__ __align__(256) float g_ao[(size_t)MTOK * Dm];
__device__ __align__(256) float g_at[(size_t)MTOK * Dm];
__device__ __align__(256) float g_ln[(size_t)MTOK * Dm];
__device__ __align__(256) float g_h1[(size_t)MTOK * FF];

// ----------------------------------------------------------------------------
// Baseline-PTX helpers (no 'a'-gated instructions — harness compiles compute_103)
// ----------------------------------------------------------------------------
__device__ __forceinline__ uint32_t smem_u32(const void* p) {
    uint32_t a;
    asm("{ .reg .u64 t; cvta.to.shared.u64 t, %1; cvt.u32.u64 %0, t; }" : "=r"(a) : "l"(p));
    return a;
}
__device__ __forceinline__ void cpa16(void* dst, const void* src) {
    uint32_t d = smem_u32(dst);
    asm volatile("cp.async.cg.shared.global [%0], [%1], 16;" :: "r"(d), "l"(src) : "memory");
}
// Activations are pre-rounded to tf32 (RNA) by producers, so raw-bit
// truncation here is lossless for them; weights take one-sided truncation.
__device__ __forceinline__ uint32_t f2tf(float f) {
    return __float_as_uint(f);
}
// RNA tf32 rounding (producer epilogues only — never in the GEMM inner loop)
__device__ __forceinline__ float rndtf(float f) {
    uint32_t u;
    asm("cvt.rna.tf32.f32 %0, %1;" : "=r"(u) : "f"(f));
    return __uint_as_float(u);
}
__device__ __forceinline__ void mma8(float* c, const uint32_t* a, uint32_t b0, uint32_t b1) {
    asm volatile(
        "mma.sync.aligned.m16n8k8.row.col.f32.tf32.tf32.f32 "
        "{%0,%1,%2,%3}, {%4,%5,%6,%7}, {%8,%9}, {%0,%1,%2,%3};"
        : "+f"(c[0]), "+f"(c[1]), "+f"(c[2]), "+f"(c[3])
        : "r"(a[0]), "r"(a[1]), "r"(a[2]), "r"(a[3]), "r"(b0), "r"(b1));
}

// ----------------------------------------------------------------------------
// Tensor-core (mma.sync tf32) GEMM — the R7 measured-fastest configuration:
// 128xBN CTA, 256 threads, 8 warps of 32x64, K slab 32, double-buffered
// cp.async, 2 CTAs/SM.
// A row-major [m][k]. B: TB=false -> B[k][n]; TB=true -> B[n][k].
// Two-level batch z -> (z/zdiv, z%zdiv) with elementwise strides.
// Epilogue: +bias[n], *softplus-q-scale(n&63), ReLU, +resid, tf32-round (rnd).
// causal:   skip C tiles fully above the diagonal (scores GEMM).
// causalK:  clamp K loop to m0+BM (PV GEMM; P is exactly 0 for s > t).
// ----------------------------------------------------------------------------
constexpr int BM = 128;
constexpr int BK = 32;

template <int BN, bool TB>
__global__ void __launch_bounds__(256, 2) gemm_mma(
    const float* __restrict__ A, const float* __restrict__ B, float* __restrict__ C,
    int K, int lda, int ldb, int ldc, int zdiv,
    long long sA1, long long sA2, long long sB1, long long sB2,
    long long sC1, long long sC2,
    const float* __restrict__ bias, const float* __restrict__ resid,
    const float* __restrict__ pds, int relu, int causal, int causalK, int rnd)
{
    constexpr int AW = BK + 4;                 // A row words (pad 4 -> conflict-free frags)
    constexpr int BW = TB ? (BK + 4) : (BN + 8);
    constexpr int AS = BM * AW;
    constexpr int BS = TB ? BN * BW : BK * BW;
    constexpr int STW = AS + BS;               // words per stage
    constexpr int NT = BN / 16;                // n-subtiles per warp (warp covers BN/2 cols)
    extern __shared__ float sm[];

    int m0 = blockIdx.y * BM;
    int n0 = blockIdx.x * BN;
    if (causal && n0 > m0 + BM - 1) return;

    int z = blockIdx.z, z1 = z / zdiv, z2 = z - z1 * zdiv;
    A += z1 * sA1 + z2 * sA2;
    B += z1 * sB1 + z2 * sB2;
    long long oC = z1 * sC1 + z2 * sC2;

    int tid  = threadIdx.x;
    int lane = tid & 31;
    int w    = tid >> 5;
    int g    = lane >> 2, tg = lane & 3;
    int wm   = (w & 3) * 32;            // warp row offset in tile
    int wn   = (w >> 2) * (BN / 2);     // warp col offset in tile

    float acc[2][NT][4];
    #pragma unroll
    for (int mt = 0; mt < 2; mt++)
        #pragma unroll
        for (int nt = 0; nt < NT; nt++)
            #pragma unroll
            for (int i = 0; i < 4; i++) acc[mt][nt][i] = 0.f;

    int Keff = K;
    if (causalK && m0 + BM < K) Keff = m0 + BM;   // P[t][s] == 0 for s > t
    int nslab = Keff / BK;

    auto loadSlab = [&](int buf, int slab) {
        float* As = sm + buf * STW;
        float* Bs = As + AS;
        int ko = slab * BK;
        #pragma unroll
        for (int i = 0; i < (BM * 8) / 256; i++) {           // A: 128 x 8 float4
            int c = tid + i * 256;
            int r = c >> 3, f = (c & 7) * 4;
            cpa16(&As[r * AW + f], A + (long long)(m0 + r) * lda + ko + f);
        }
        if (TB) {
            #pragma unroll
            for (int i = 0; i < (BN * 8) / 256; i++) {       // B: BN x 8 float4
                int c = tid + i * 256;
                int r = c >> 3, f = (c & 7) * 4;
                cpa16(&Bs[r * BW + f], B + (long long)(n0 + r) * ldb + ko + f);
            }
        } else {
            #pragma unroll
            for (int i = 0; i < (BK * (BN / 4)) / 256; i++) { // B: 32 x (BN/4) float4
                int c = tid + i * 256;
                int r = c / (BN / 4), f = (c % (BN / 4)) * 4;
                cpa16(&Bs[r * BW + f], B + (long long)(ko + r) * ldb + n0 + f);
            }
        }
        asm volatile("cp.async.commit_group;" ::: "memory");
    };

    auto compute = [&](int buf) {
        const float* As = sm + buf * STW;
        const float* Bs = As + AS;
        #pragma unroll
        for (int kk = 0; kk < 4; kk++) {
            int k = kk * 8;
            uint32_t af[2][4];
            #pragma unroll
            for (int mt = 0; mt < 2; mt++) {
                int r = wm + mt * 16 + g;
                af[mt][0] = f2tf(As[r * AW + k + tg]);
                af[mt][1] = f2tf(As[(r + 8) * AW + k + tg]);
                af[mt][2] = f2tf(As[r * AW + k + tg + 4]);
                af[mt][3] = f2tf(As[(r + 8) * AW + k + tg + 4]);
            }
            #pragma unroll
            for (int nt = 0; nt < NT; nt++) {
                int cn = wn + nt * 8 + g;
                uint32_t b0, b1;
                if (TB) {
                    b0 = f2tf(Bs[cn * BW + k + tg]);
                    b1 = f2tf(Bs[cn * BW + k + tg + 4]);
                } else {
                    b0 = f2tf(Bs[(k + tg) * BW + cn]);
                    b1 = f2tf(Bs[(k + tg + 4) * BW + cn]);
                }
                #pragma unroll
                for (int mt = 0; mt < 2; mt++)
                    mma8(acc[mt][nt], af[mt], b0, b1);
            }
        }
    };

    loadSlab(0, 0);
    for (int s = 0; s < nslab; s++) {
        if (s + 1 < nslab) {
            loadSlab((s + 1) & 1, s + 1);
            asm volatile("cp.async.wait_group 1;" ::: "memory");
        } else {
            asm volatile("cp.async.wait_group 0;" ::: "memory");
        }
        __syncthreads();
        compute(s & 1);
        __syncthreads();
    }

    // Epilogue
    float* Cb = C + oC;
    const float* Rb = resid ? resid + oC : nullptr;
    #pragma unroll
    for (int mt = 0; mt < 2; mt++) {
        #pragma unroll
        for (int nt = 0; nt < NT; nt++) {
            int cn = n0 + wn + nt * 8 + 2 * tg;
            float bv0 = 0.f, bv1 = 0.f, s0 = 1.f, s1 = 1.f;
            if (bias) { bv0 = bias[cn]; bv1 = bias[cn + 1]; }
            if (pds) {
                float p0 = pds[cn & (HD - 1)], p1 = pds[(cn + 1) & (HD - 1)];
                float sp0 = (p0 > 20.f) ? p0 : log1pf(expf(p0));
                float sp1 = (p1 > 20.f) ? p1 : log1pf(expf(p1));
                s0 = 0.1803368801111f * sp0;   // log2(e)/sqrt(64) * softplus
                s1 = 0.1803368801111f * sp1;
            }
            #pragma unroll
            for (int h = 0; h < 2; h++) {
                int r = m0 + wm + mt * 16 + g + h * 8;
                float v0 = acc[mt][nt][h * 2 + 0];
                float v1 = acc[mt][nt][h * 2 + 1];
                if (bias) { v0 += bv0; v1 += bv1; }
                if (pds)  { v0 *= s0; v1 *= s1; }
                if (relu) { v0 = fmaxf(v0, 0.f); v1 = fmaxf(v1, 0.f); }
                long long off = (long long)r * ldc + cn;
                if (Rb) {
                    float2 rr = *reinterpret_cast<const float2*>(Rb + off);
                    v0 += rr.x; v1 += rr.y;
                }
                if (rnd) { v0 = rndtf(v0); v1 = rndtf(v1); }
                *reinterpret_cast<float2*>(Cb + off) = make_float2(v0, v1);
            }
        }
    }
}

// ----------------------------------------------------------------------------
// Elementwise kernels
// ----------------------------------------------------------------------------
__device__ __forceinline__ float warpSum(float v) {
    #pragma unroll
    for (int o = 16; o > 0; o >>= 1) v += __shfl_xor_sync(0xffffffffu, v, o);
    return v;
}
__device__ __forceinline__ float warpMax(float v) {
    #pragma unroll
    for (int o = 16; o > 0; o >>= 1) v = fmaxf(v, __shfl_xor_sync(0xffffffffu, v, o));
    return v;
}

__global__ void __launch_bounds__(256) rmsnorm_k(const float* __restrict__ x,
                                                 const float* __restrict__ g,
                                                 float* __restrict__ out) {
    size_t base = (size_t)blockIdx.x * Dm;
    int tid = threadIdx.x;
    float4 xv = reinterpret_cast<const float4*>(x + base)[tid];
    float ss = xv.x * xv.x + xv.y * xv.y + xv.z * xv.z + xv.w * xv.w;
    __shared__ float sh[8];
    __shared__ float bval;
    ss = warpSum(ss);
    if ((tid & 31) == 0) sh[tid >> 5] = ss;
    __syncthreads();
    if (tid == 0) {
        float s = 0.f;
        #pragma unroll
        for (int i = 0; i < 8; i++) s += sh[i];
        bval = s;
    }
    __syncthreads();
    float r = rsqrtf(bval * (1.0f / Dm) + 1e-6f);
    float4 gv = reinterpret_cast<const float4*>(g)[tid];
    reinterpret_cast<float4*>(out + base)[tid] =
        make_float4(rndtf(xv.x * r * gv.x), rndtf(xv.y * r * gv.y),
                    rndtf(xv.z * r * gv.z), rndtf(xv.w * r * gv.w));
}

__global__ void __launch_bounds__(256) layernorm_k(const float* __restrict__ x,
                                                   const float* __restrict__ gamma,
                                                   const float* __restrict__ beta,
                                                   float* __restrict__ out) {
    size_t base = (size_t)blockIdx.x * Dm;
    int tid = threadIdx.x;
    float4 xv = reinterpret_cast<const float4*>(x + base)[tid];
    float s1 = xv.x + xv.y + xv.z + xv.w;
    float s2 = xv.x * xv.x + xv.y * xv.y + xv.z * xv.z + xv.w * xv.w;
    __shared__ float shA[8], shB[8];
    __shared__ float bm, bv2;
    s1 = warpSum(s1);
    s2 = warpSum(s2);
    if ((tid & 31) == 0) { shA[tid >> 5] = s1; shB[tid >> 5] = s2; }
    __syncthreads();
    if (tid == 0) {
        float a = 0.f, b = 0.f;
        #pragma unroll
        for (int i = 0; i < 8; i++) { a += shA[i]; b += shB[i]; }
        bm = a * (1.0f / Dm); bv2 = b * (1.0f / Dm);
    }
    __syncthreads();
    float mean = bm;
    float r = rsqrtf(bv2 - mean * mean + 1e-5f);
    float4 gv = reinterpret_cast<const float4*>(gamma)[tid];
    float4 bvv = reinterpret_cast<const float4*>(beta)[tid];
    reinterpret_cast<float4*>(out + base)[tid] =
        make_float4(rndtf((xv.x - mean) * r * gv.x + bvv.x),
                    rndtf((xv.y - mean) * r * gv.y + bvv.y),
                    rndtf((xv.z - mean) * r * gv.z + bvv.z),
                    rndtf((xv.w - mean) * r * gv.w + bvv.w));
}

// Masked softmax, causal-limited: only s < L = roundup128(t+1) is ever read
// downstream (PV clamps K to the diagonal tile), and scores beyond L were
// never written by the causal-skipped scores GEMM. Output rounded to tf32.
__global__ void __launch_bounds__(256) softmax_k(float* __restrict__ sc,
                                                 const float* __restrict__ padding) {
    int t = blockIdx.x;
    int z = blockIdx.y;
    int b = z >> 4;
    int L = ((t >> 7) + 1) << 7;              // tile-rounded causal length
    float* row = sc + ((size_t)z * T + t) * T;
    int tid = threadIdx.x;
    int s0 = tid * 4;
    bool act = s0 < L;

    float vals[4] = {-1e9f, -1e9f, -1e9f, -1e9f};
    if (act) {
        float4 rv = reinterpret_cast<float4*>(row)[tid];
        float4 pv = reinterpret_cast<const float4*>(padding + (size_t)b * T)[tid];
        float padt = padding[(size_t)b * T + t];
        float vv[4] = {rv.x, rv.y, rv.z, rv.w};
        float pp[4] = {pv.x, pv.y, pv.z, pv.w};
        #pragma unroll
        for (int i = 0; i < 4; i++) {
            bool ok = (s0 + i <= t) && (padt != 0.f) && (pp[i] != 0.f);
            vals[i] = ok ? vv[i] : -1e9f;
        }
    }
    float mx = fmaxf(fmaxf(vals[0], vals[1]), fmaxf(vals[2], vals[3]));

    __shared__ float sh[8];
    __shared__ float bmax, bsum;
    mx = warpMax(mx);
    if ((tid & 31) == 0) sh[tid >> 5] = mx;
    __syncthreads();
    if (tid == 0) {
        float m = sh[0];
        #pragma unroll
        for (int i = 1; i < 8; i++) m = fmaxf(m, sh[i]);
        bmax = m;
    }
    __syncthreads();
    mx = bmax;
    float e[4], ls = 0.f;
    #pragma unroll
    for (int i = 0; i < 4; i++) { e[i] = __expf(vals[i] - mx); ls += e[i]; }
    ls = warpSum(ls);
    if ((tid & 31) == 0) sh[tid >> 5] = ls;
    __syncthreads();
    if (tid == 0) {
        float s = 0.f;
        #pragma unroll
        for (int i = 0; i < 8; i++) s += sh[i];
        bsum = s;
    }
    __syncthreads();
    float inv = 1.0f / bsum;
    if (act) {
        reinterpret_cast<float4*>(row)[tid] =
            make_float4(rndtf(e[0] * inv), rndtf(e[1] * inv),
                        rndtf(e[2] * inv), rndtf(e[3] * inv));
    }
}

// ----------------------------------------------------------------------------
// Launch
// ----------------------------------------------------------------------------
extern "C" void kernel_launch(void* const* d_in, const int* in_sizes, int n_in,
                              void* d_out, int out_size) {
    const float* x    = (const float*)d_in[0];
    const float* pad  = (const float*)d_in[1];
    const float* rmss = (const float*)d_in[2];
    const float* pds  = (const float*)d_in[3];
    const float* wq   = (const float*)d_in[4];
    const float* bq   = (const float*)d_in[5];
    const float* wk   = (const float*)d_in[6];
    const float* bk   = (const float*)d_in[7];
    const float* wv   = (const float*)d_in[8];
    const float* bv   = (const float*)d_in[9];
    const float* wo   = (const float*)d_in[10];
    const float* bo   = (const float*)d_in[11];
    const float* lng  = (const float*)d_in[12];
    const float* lnb  = (const float*)d_in[13];
    const float* w1   = (const float*)d_in[14];
    const float* b1   = (const float*)d_in[15];
    const float* w2   = (const float*)d_in[16];
    const float* b2   = (const float*)d_in[17];
    float* out = (float*)d_out;

    float *xn, *q, *k, *v, *sc, *ao, *at, *ln, *h1;
    cudaGetSymbolAddress((void**)&xn, g_xn);
    cudaGetSymbolAddress((void**)&q,  g_q);
    cudaGetSymbolAddress((void**)&k,  g_k);
    cudaGetSymbolAddress((void**)&v,  g_v);
    cudaGetSymbolAddress((void**)&sc, g_sc);
    cudaGetSymbolAddress((void**)&ao, g_ao);
    cudaGetSymbolAddress((void**)&at, g_at);
    cudaGetSymbolAddress((void**)&ln, g_ln);
    cudaGetSymbolAddress((void**)&h1, g_h1);

    // Dynamic smem sizes (bytes) per instantiation
    const int SMF128 = (BM * 36 + BK * 136) * 2 * 4;   // <128,false> : 71680
    const int SMT128 = (BM * 36 + 128 * 36) * 2 * 4;   // <128,true>  : 73728
    const int SMF64  = (BM * 36 + BK * 72) * 2 * 4;    // <64,false>  : 55296
    cudaFuncSetAttribute(gemm_mma<128, false>, cudaFuncAttributeMaxDynamicSharedMemorySize, SMF128);
    cudaFuncSetAttribute(gemm_mma<128, true>,  cudaFuncAttributeMaxDynamicSharedMemorySize, SMT128);
    cudaFuncSetAttribute(gemm_mma<64,  false>, cudaFuncAttributeMaxDynamicSharedMemorySize, SMF64);

    const long long Z = 0;

    // 1. RMSNorm (tf32-rounded output)
    rmsnorm_k<<<MTOK, 256>>>(x, rmss, xn);

    // 2. Q/K/V projections (rounded outputs; Q fuses bias + softplus scale)
    gemm_mma<128, false><<<dim3(Dm / 128, MTOK / 128, 1), 256, SMF128>>>(
        xn, wq, q, Dm, Dm, Dm, Dm, 1, Z, Z, Z, Z, Z, Z, bq, nullptr, pds, 0, 0, 0, 1);
    gemm_mma<128, false><<<dim3(Dm / 128, MTOK / 128, 1), 256, SMF128>>>(
        xn, wk, k, Dm, Dm, Dm, Dm, 1, Z, Z, Z, Z, Z, Z, bk, nullptr, nullptr, 0, 0, 0, 1);
    gemm_mma<128, false><<<dim3(Dm / 128, MTOK / 128, 1), 256, SMF128>>>(
        xn, wv, v, Dm, Dm, Dm, Dm, 1, Z, Z, Z, Z, Z, Z, bv, nullptr, nullptr, 0, 0, 0, 1);

    // 3. scores[b,n,t,s] = Q K^T (batched over b,n; causal tile skip)
    gemm_mma<128, true><<<dim3(T / 128, T / 128, Bb * NH), 256, SMT128>>>(
        q, k, sc, HD, Dm, Dm, T, NH,
        (long long)T * Dm, (long long)HD,
        (long long)T * Dm, (long long)HD,
        (long long)NH * T * T, (long long)T * T,
        nullptr, nullptr, nullptr, 0, 1, 0, 0);

    // 4. masked softmax (causal-limited, rounded output)
    softmax_k<<<dim3(T, Bb * NH), 256>>>(sc, pad);

    // 5. attn_out[b,t,n,h] = P V (K clamped to diagonal; rounded output)
    gemm_mma<64, false><<<dim3(1, T / 128, Bb * NH), 256, SMF64>>>(
        sc, v, ao, T, T, Dm, Dm, NH,
        (long long)NH * T * T, (long long)T * T,
        (long long)T * Dm, (long long)HD,
        (long long)T * Dm, (long long)HD,
        nullptr, nullptr, nullptr, 0, 0, 1, 1);

    // 6. out-proj + bo + residual(x)  (exact fp32 output)
    gemm_mma<128, true><<<dim3(Dm / 128, MTOK / 128, 1), 256, SMT128>>>(
        ao, wo, at, Dm, Dm, Dm, Dm, 1, Z, Z, Z, Z, Z, Z, bo, x, nullptr, 0, 0, 0, 0);

    // 7. LayerNorm (rounded output)
    layernorm_k<<<MTOK, 256>>>(at, lng, lnb, ln);

    // 8. FFN1 + ReLU (rounded output)
    gemm_mma<128, false><<<dim3(FF / 128, MTOK / 128, 1), 256, SMF128>>>(
        ln, w1, h1, Dm, Dm, FF, FF, 1, Z, Z, Z, Z, Z, Z, b1, nullptr, nullptr, 1, 0, 0, 1);

    // 9. FFN2 + b2 + residual(at) -> out (exact fp32 output)
    gemm_mma<128, false><<<dim3(Dm / 128, MTOK / 128, 1), 256, SMF128>>>(
        h1, w2, out, FF, FF, Dm, Dm, 1, Z, Z, Z, Z, Z, Z, b2, at, nullptr, 0, 0, 0, 0);
}

// round 12
// speedup vs baseline: 1.0598x; 1.0067x over previous
#include <cuda_runtime.h>
#include <math.h>
#include <stdint.h>

// Problem constants
constexpr int Bb   = 8;
constexpr int T    = 1024;
constexpr int Dm   = 1024;
constexpr int NH   = 16;
constexpr int HD   = 64;
constexpr int FF   = 4096;
constexpr int MTOK = Bb * T;            // 8192 tokens

// ----------------------------------------------------------------------------
// Scratch (allocation-free: __device__ globals)
// ----------------------------------------------------------------------------
__device__ __align__(256) float g_xn[(size_t)MTOK * Dm];
__device__ __align__(256) float g_q [(size_t)MTOK * Dm];
__device__ __align__(256) float g_k [(size_t)MTOK * Dm];
__device__ __align__(256) float g_v [(size_t)MTOK * Dm];
__device__ __align__(256) float g_sc[(size_t)Bb * NH * T * T];   // 512 MB scores
__device__ __align__(256) float g_ao[(size_t)MTOK * Dm];
__device__ __align__(256) float g_at[(size_t)MTOK * Dm];
__device__ __align__(256) float g_ln[(size_t)MTOK * Dm];
__device__ __align__(256) float g_h1[(size_t)MTOK * FF];

// ----------------------------------------------------------------------------
// Baseline-PTX helpers (no 'a'-gated instructions — harness compiles compute_103)
// ----------------------------------------------------------------------------
__device__ __forceinline__ uint32_t smem_u32(const void* p) {
    uint32_t a;
    asm("{ .reg .u64 t; cvta.to.shared.u64 t, %1; cvt.u32.u64 %0, t; }" : "=r"(a) : "l"(p));
    return a;
}
__device__ __forceinline__ void cpa16(void* dst, const void* src) {
    uint32_t d = smem_u32(dst);
    asm volatile("cp.async.cg.shared.global [%0], [%1], 16;" :: "r"(d), "l"(src) : "memory");
}
// Activations are pre-rounded to tf32 (RNA) by producers, so raw-bit
// truncation here is lossless for them; weights take one-sided truncation.
__device__ __forceinline__ uint32_t f2tf(float f) {
    return __float_as_uint(f);
}
// RNA tf32 rounding (producer epilogues only — never in the GEMM inner loop)
__device__ __forceinline__ float rndtf(float f) {
    uint32_t u;
    asm("cvt.rna.tf32.f32 %0, %1;" : "=r"(u) : "f"(f));
    return __uint_as_float(u);
}
__device__ __forceinline__ void mma8(float* c, const uint32_t* a, uint32_t b0, uint32_t b1) {
    asm volatile(
        "mma.sync.aligned.m16n8k8.row.col.f32.tf32.tf32.f32 "
        "{%0,%1,%2,%3}, {%4,%5,%6,%7}, {%8,%9}, {%0,%1,%2,%3};"
        : "+f"(c[0]), "+f"(c[1]), "+f"(c[2]), "+f"(c[3])
        : "r"(a[0]), "r"(a[1]), "r"(a[2]), "r"(a[3]), "r"(b0), "r"(b1));
}
// ldmatrix on f32 data: each 8x8 b16 matrix = 8x4 f32 chunk (16B rows);
// lane l receives f32 element [row l/4][col l%4] — exactly the tf32 mma
// fragment distribution. x4 = full m16k8 A fragment; x2 = m8k8 B fragment.
__device__ __forceinline__ void ldm4(uint32_t* r, uint32_t addr) {
    asm volatile("ldmatrix.sync.aligned.m8n8.x4.shared.b16 {%0,%1,%2,%3}, [%4];"
                 : "=r"(r[0]), "=r"(r[1]), "=r"(r[2]), "=r"(r[3]) : "r"(addr));
}
__device__ __forceinline__ void ldm2(uint32_t* r, uint32_t addr) {
    asm volatile("ldmatrix.sync.aligned.m8n8.x2.shared.b16 {%0,%1}, [%2];"
                 : "=r"(r[0]), "=r"(r[1]) : "r"(addr));
}

// ----------------------------------------------------------------------------
// Tensor-core (mma.sync tf32) GEMM — R7 config + ldmatrix fragment loads:
// 128xBN CTA, 256 threads, 8 warps of 32x64, K slab 32, double-buffered
// cp.async, 2 CTAs/SM.
// A row-major [m][k]. B: TB=false -> B[k][n]; TB=true -> B[n][k].
// Two-level batch z -> (z/zdiv, z%zdiv) with elementwise strides.
// Epilogue: +bias[n], *softplus-q-scale(n&63), ReLU, +resid, tf32-round (rnd).
// causal:   skip C tiles fully above the diagonal (scores GEMM).
// causalK:  clamp K loop to m0+BM (PV GEMM; P is exactly 0 for s > t).
// ----------------------------------------------------------------------------
constexpr int BM = 128;
constexpr int BK = 32;

template <int BN, bool TB>
__global__ void __launch_bounds__(256, 2) gemm_mma(
    const float* __restrict__ A, const float* __restrict__ B, float* __restrict__ C,
    int K, int lda, int ldb, int ldc, int zdiv,
    long long sA1, long long sA2, long long sB1, long long sB2,
    long long sC1, long long sC2,
    const float* __restrict__ bias, const float* __restrict__ resid,
    const float* __restrict__ pds, int relu, int causal, int causalK, int rnd)
{
    constexpr int AW = BK + 4;                 // A row words (stride 144B: conflict-free ldmatrix)
    constexpr int BW = TB ? (BK + 4) : (BN + 8);
    constexpr int AS = BM * AW;
    constexpr int BS = TB ? BN * BW : BK * BW;
    constexpr int STW = AS + BS;               // words per stage
    constexpr int NT = BN / 16;                // n-subtiles per warp (warp covers BN/2 cols)
    extern __shared__ float sm[];

    int m0 = blockIdx.y * BM;
    int n0 = blockIdx.x * BN;
    if (causal && n0 > m0 + BM - 1) return;

    int z = blockIdx.z, z1 = z / zdiv, z2 = z - z1 * zdiv;
    A += z1 * sA1 + z2 * sA2;
    B += z1 * sB1 + z2 * sB2;
    long long oC = z1 * sC1 + z2 * sC2;

    int tid  = threadIdx.x;
    int lane = tid & 31;
    int w    = tid >> 5;
    int g    = lane >> 2, tg = lane & 3;
    int wm   = (w & 3) * 32;            // warp row offset in tile
    int wn   = (w >> 2) * (BN / 2);     // warp col offset in tile

    float acc[2][NT][4];
    #pragma unroll
    for (int mt = 0; mt < 2; mt++)
        #pragma unroll
        for (int nt = 0; nt < NT; nt++)
            #pragma unroll
            for (int i = 0; i < 4; i++) acc[mt][nt][i] = 0.f;

    int Keff = K;
    if (causalK && m0 + BM < K) Keff = m0 + BM;   // P[t][s] == 0 for s > t
    int nslab = Keff / BK;

    // ldmatrix lane base offsets (words) within a stage
    uint32_t smBase = smem_u32(sm);
    // A: lanes 0-15 -> rows wm+(l&15) col 0; lanes 16-31 -> same rows col 4
    uint32_t aOff = (uint32_t)((wm + (lane & 15)) * AW + (lane >> 4) * 4) * 4;
    // B (TB): lanes 0-7 -> rows wn+(l&7) col 0; lanes 8-15 -> col 4
    uint32_t bOff = (uint32_t)((wn + (lane & 7)) * BW + ((lane >> 3) & 1) * 4) * 4;

    auto loadSlab = [&](int buf, int slab) {
        float* As = sm + buf * STW;
        float* Bs = As + AS;
        int ko = slab * BK;
        #pragma unroll
        for (int i = 0; i < (BM * 8) / 256; i++) {           // A: 128 x 8 float4
            int c = tid + i * 256;
            int r = c >> 3, f = (c & 7) * 4;
            cpa16(&As[r * AW + f], A + (long long)(m0 + r) * lda + ko + f);
        }
        if (TB) {
            #pragma unroll
            for (int i = 0; i < (BN * 8) / 256; i++) {       // B: BN x 8 float4
                int c = tid + i * 256;
                int r = c >> 3, f = (c & 7) * 4;
                cpa16(&Bs[r * BW + f], B + (long long)(n0 + r) * ldb + ko + f);
            }
        } else {
            #pragma unroll
            for (int i = 0; i < (BK * (BN / 4)) / 256; i++) { // B: 32 x (BN/4) float4
                int c = tid + i * 256;
                int r = c / (BN / 4), f = (c % (BN / 4)) * 4;
                cpa16(&Bs[r * BW + f], B + (long long)(ko + r) * ldb + n0 + f);
            }
        }
        asm volatile("cp.async.commit_group;" ::: "memory");
    };

    auto compute = [&](int buf) {
        uint32_t stBase = smBase + (uint32_t)(buf * STW) * 4;
        uint32_t aB = stBase + aOff;
        uint32_t bB = stBase + (uint32_t)AS * 4 + bOff;
        const float* Bs = sm + buf * STW + AS;
        #pragma unroll
        for (int kk = 0; kk < 4; kk++) {
            int k = kk * 8;
            uint32_t af[2][4];
            ldm4(af[0], aB + k * 4);                    // rows wm..wm+15
            ldm4(af[1], aB + 16 * AW * 4 + k * 4);      // rows wm+16..wm+31
            #pragma unroll
            for (int nt = 0; nt < NT; nt++) {
                uint32_t b[2];
                if (TB) {
                    ldm2(b, bB + nt * 8 * BW * 4 + k * 4);
                } else {
                    int cn = wn + nt * 8 + g;
                    b[0] = f2tf(Bs[(k + tg) * BW + cn]);
                    b[1] = f2tf(Bs[(k + tg + 4) * BW + cn]);
                }
                mma8(acc[0][nt], af[0], b[0], b[1]);
                mma8(acc[1][nt], af[1], b[0], b[1]);
            }
        }
    };

    loadSlab(0, 0);
    for (int s = 0; s < nslab; s++) {
        if (s + 1 < nslab) {
            loadSlab((s + 1) & 1, s + 1);
            asm volatile("cp.async.wait_group 1;" ::: "memory");
        } else {
            asm volatile("cp.async.wait_group 0;" ::: "memory");
        }
        __syncthreads();
        compute(s & 1);
        __syncthreads();
    }

    // Epilogue
    float* Cb = C + oC;
    const float* Rb = resid ? resid + oC : nullptr;
    #pragma unroll
    for (int mt = 0; mt < 2; mt++) {
        #pragma unroll
        for (int nt = 0; nt < NT; nt++) {
            int cn = n0 + wn + nt * 8 + 2 * tg;
            float bv0 = 0.f, bv1 = 0.f, s0 = 1.f, s1 = 1.f;
            if (bias) { bv0 = bias[cn]; bv1 = bias[cn + 1]; }
            if (pds) {
                float p0 = pds[cn & (HD - 1)], p1 = pds[(cn + 1) & (HD - 1)];
                float sp0 = (p0 > 20.f) ? p0 : log1pf(expf(p0));
                float sp1 = (p1 > 20.f) ? p1 : log1pf(expf(p1));
                s0 = 0.1803368801111f * sp0;   // log2(e)/sqrt(64) * softplus
                s1 = 0.1803368801111f * sp1;
            }
            #pragma unroll
            for (int h = 0; h < 2; h++) {
                int r = m0 + wm + mt * 16 + g + h * 8;
                float v0 = acc[mt][nt][h * 2 + 0];
                float v1 = acc[mt][nt][h * 2 + 1];
                if (bias) { v0 += bv0; v1 += bv1; }
                if (pds)  { v0 *= s0; v1 *= s1; }
                if (relu) { v0 = fmaxf(v0, 0.f); v1 = fmaxf(v1, 0.f); }
                long long off = (long long)r * ldc + cn;
                if (Rb) {
                    float2 rr = *reinterpret_cast<const float2*>(Rb + off);
                    v0 += rr.x; v1 += rr.y;
                }
                if (rnd) { v0 = rndtf(v0); v1 = rndtf(v1); }
                *reinterpret_cast<float2*>(Cb + off) = make_float2(v0, v1);
            }
        }
    }
}

// ----------------------------------------------------------------------------
// Elementwise kernels
// ----------------------------------------------------------------------------
__device__ __forceinline__ float warpSum(float v) {
    #pragma unroll
    for (int o = 16; o > 0; o >>= 1) v += __shfl_xor_sync(0xffffffffu, v, o);
    return v;
}
__device__ __forceinline__ float warpMax(float v) {
    #pragma unroll
    for (int o = 16; o > 0; o >>= 1) v = fmaxf(v, __shfl_xor_sync(0xffffffffu, v, o));
    return v;
}

__global__ void __launch_bounds__(256) rmsnorm_k(const float* __restrict__ x,
                                                 const float* __restrict__ g,
                                                 float* __restrict__ out) {
    size_t base = (size_t)blockIdx.x * Dm;
    int tid = threadIdx.x;
    float4 xv = reinterpret_cast<const float4*>(x + base)[tid];
    float ss = xv.x * xv.x + xv.y * xv.y + xv.z * xv.z + xv.w * xv.w;
    __shared__ float sh[8];
    __shared__ float bval;
    ss = warpSum(ss);
    if ((tid & 31) == 0) sh[tid >> 5] = ss;
    __syncthreads();
    if (tid == 0) {
        float s = 0.f;
        #pragma unroll
        for (int i = 0; i < 8; i++) s += sh[i];
        bval = s;
    }
    __syncthreads();
    float r = rsqrtf(bval * (1.0f / Dm) + 1e-6f);
    float4 gv = reinterpret_cast<const float4*>(g)[tid];
    reinterpret_cast<float4*>(out + base)[tid] =
        make_float4(rndtf(xv.x * r * gv.x), rndtf(xv.y * r * gv.y),
                    rndtf(xv.z * r * gv.z), rndtf(xv.w * r * gv.w));
}

__global__ void __launch_bounds__(256) layernorm_k(const float* __restrict__ x,
                                                   const float* __restrict__ gamma,
                                                   const float* __restrict__ beta,
                                                   float* __restrict__ out) {
    size_t base = (size_t)blockIdx.x * Dm;
    int tid = threadIdx.x;
    float4 xv = reinterpret_cast<const float4*>(x + base)[tid];
    float s1 = xv.x + xv.y + xv.z + xv.w;
    float s2 = xv.x * xv.x + xv.y * xv.y + xv.z * xv.z + xv.w * xv.w;
    __shared__ float shA[8], shB[8];
    __shared__ float bm, bv2;
    s1 = warpSum(s1);
    s2 = warpSum(s2);
    if ((tid & 31) == 0) { shA[tid >> 5] = s1; shB[tid >> 5] = s2; }
    __syncthreads();
    if (tid == 0) {
        float a = 0.f, b = 0.f;
        #pragma unroll
        for (int i = 0; i < 8; i++) { a += shA[i]; b += shB[i]; }
        bm = a * (1.0f / Dm); bv2 = b * (1.0f / Dm);
    }
    __syncthreads();
    float mean = bm;
    float r = rsqrtf(bv2 - mean * mean + 1e-5f);
    float4 gv = reinterpret_cast<const float4*>(gamma)[tid];
    float4 bvv = reinterpret_cast<const float4*>(beta)[tid];
    reinterpret_cast<float4*>(out + base)[tid] =
        make_float4(rndtf((xv.x - mean) * r * gv.x + bvv.x),
                    rndtf((xv.y - mean) * r * gv.y + bvv.y),
                    rndtf((xv.z - mean) * r * gv.z + bvv.z),
                    rndtf((xv.w - mean) * r * gv.w + bvv.w));
}

// Masked softmax, causal-limited: only s < L = roundup128(t+1) is ever read
// downstream (PV clamps K to the diagonal tile), and scores beyond L were
// never written by the causal-skipped scores GEMM. Output rounded to tf32.
__global__ void __launch_bounds__(256) softmax_k(float* __restrict__ sc,
                                                 const float* __restrict__ padding) {
    int t = blockIdx.x;
    int z = blockIdx.y;
    int b = z >> 4;
    int L = ((t >> 7) + 1) << 7;              // tile-rounded causal length
    float* row = sc + ((size_t)z * T + t) * T;
    int tid = threadIdx.x;
    int s0 = tid * 4;
    bool act = s0 < L;

    float vals[4] = {-1e9f, -1e9f, -1e9f, -1e9f};
    if (act) {
        float4 rv = reinterpret_cast<float4*>(row)[tid];
        float4 pv = reinterpret_cast<const float4*>(padding + (size_t)b * T)[tid];
        float padt = padding[(size_t)b * T + t];
        float vv[4] = {rv.x, rv.y, rv.z, rv.w};
        float pp[4] = {pv.x, pv.y, pv.z, pv.w};
        #pragma unroll
        for (int i = 0; i < 4; i++) {
            bool ok = (s0 + i <= t) && (padt != 0.f) && (pp[i] != 0.f);
            vals[i] = ok ? vv[i] : -1e9f;
        }
    }
    float mx = fmaxf(fmaxf(vals[0], vals[1]), fmaxf(vals[2], vals[3]));

    __shared__ float sh[8];
    __shared__ float bmax, bsum;
    mx = warpMax(mx);
    if ((tid & 31) == 0) sh[tid >> 5] = mx;
    __syncthreads();
    if (tid == 0) {
        float m = sh[0];
        #pragma unroll
        for (int i = 1; i < 8; i++) m = fmaxf(m, sh[i]);
        bmax = m;
    }
    __syncthreads();
    mx = bmax;
    float e[4], ls = 0.f;
    #pragma unroll
    for (int i = 0; i < 4; i++) { e[i] = __expf(vals[i] - mx); ls += e[i]; }
    ls = warpSum(ls);
    if ((tid & 31) == 0) sh[tid >> 5] = ls;
    __syncthreads();
    if (tid == 0) {
        float s = 0.f;
        #pragma unroll
        for (int i = 0; i < 8; i++) s += sh[i];
        bsum = s;
    }
    __syncthreads();
    float inv = 1.0f / bsum;
    if (act) {
        reinterpret_cast<float4*>(row)[tid] =
            make_float4(rndtf(e[0] * inv), rndtf(e[1] * inv),
                        rndtf(e[2] * inv), rndtf(e[3] * inv));
    }
}

// ----------------------------------------------------------------------------
// Launch
// ----------------------------------------------------------------------------
extern "C" void kernel_launch(void* const* d_in, const int* in_sizes, int n_in,
                              void* d_out, int out_size) {
    const float* x    = (const float*)d_in[0];
    const float* pad  = (const float*)d_in[1];
    const float* rmss = (const float*)d_in[2];
    const float* pds  = (const float*)d_in[3];
    const float* wq   = (const float*)d_in[4];
    const float* bq   = (const float*)d_in[5];
    const float* wk   = (const float*)d_in[6];
    const float* bk   = (const float*)d_in[7];
    const float* wv   = (const float*)d_in[8];
    const float* bv   = (const float*)d_in[9];
    const float* wo   = (const float*)d_in[10];
    const float* bo   = (const float*)d_in[11];
    const float* lng  = (const float*)d_in[12];
    const float* lnb  = (const float*)d_in[13];
    const float* w1   = (const float*)d_in[14];
    const float* b1   = (const float*)d_in[15];
    const float* w2   = (const float*)d_in[16];
    const float* b2   = (const float*)d_in[17];
    float* out = (float*)d_out;

    float *xn, *q, *k, *v, *sc, *ao, *at, *ln, *h1;
    cudaGetSymbolAddress((void**)&xn, g_xn);
    cudaGetSymbolAddress((void**)&q,  g_q);
    cudaGetSymbolAddress((void**)&k,  g_k);
    cudaGetSymbolAddress((void**)&v,  g_v);
    cudaGetSymbolAddress((void**)&sc, g_sc);
    cudaGetSymbolAddress((void**)&ao, g_ao);
    cudaGetSymbolAddress((void**)&at, g_at);
    cudaGetSymbolAddress((void**)&ln, g_ln);
    cudaGetSymbolAddress((void**)&h1, g_h1);

    // Dynamic smem sizes (bytes) per instantiation
    const int SMF128 = (BM * 36 + BK * 136) * 2 * 4;   // <128,false> : 71680
    const int SMT128 = (BM * 36 + 128 * 36) * 2 * 4;   // <128,true>  : 73728
    const int SMF64  = (BM * 36 + BK * 72) * 2 * 4;    // <64,false>  : 55296
    cudaFuncSetAttribute(gemm_mma<128, false>, cudaFuncAttributeMaxDynamicSharedMemorySize, SMF128);
    cudaFuncSetAttribute(gemm_mma<128, true>,  cudaFuncAttributeMaxDynamicSharedMemorySize, SMT128);
    cudaFuncSetAttribute(gemm_mma<64,  false>, cudaFuncAttributeMaxDynamicSharedMemorySize, SMF64);

    const long long Z = 0;

    // 1. RMSNorm (tf32-rounded output)
    rmsnorm_k<<<MTOK, 256>>>(x, rmss, xn);

    // 2. Q/K/V projections (rounded outputs; Q fuses bias + softplus scale)
    gemm_mma<128, false><<<dim3(Dm / 128, MTOK / 128, 1), 256, SMF128>>>(
        xn, wq, q, Dm, Dm, Dm, Dm, 1, Z, Z, Z, Z, Z, Z, bq, nullptr, pds, 0, 0, 0, 1);
    gemm_mma<128, false><<<dim3(Dm / 128, MTOK / 128, 1), 256, SMF128>>>(
        xn, wk, k, Dm, Dm, Dm, Dm, 1, Z, Z, Z, Z, Z, Z, bk, nullptr, nullptr, 0, 0, 0, 1);
    gemm_mma<128, false><<<dim3(Dm / 128, MTOK / 128, 1), 256, SMF128>>>(
        xn, wv, v, Dm, Dm, Dm, Dm, 1, Z, Z, Z, Z, Z, Z, bv, nullptr, nullptr, 0, 0, 0, 1);

    // 3. scores[b,n,t,s] = Q K^T (batched over b,n; causal tile skip)
    gemm_mma<128, true><<<dim3(T / 128, T / 128, Bb * NH), 256, SMT128>>>(
        q, k, sc, HD, Dm, Dm, T, NH,
        (long long)T * Dm, (long long)HD,
        (long long)T * Dm, (long long)HD,
        (long long)NH * T * T, (long long)T * T,
        nullptr, nullptr, nullptr, 0, 1, 0, 0);

    // 4. masked softmax (causal-limited, rounded output)
    softmax_k<<<dim3(T, Bb * NH), 256>>>(sc, pad);

    // 5. attn_out[b,t,n,h] = P V (K clamped to diagonal; rounded output)
    gemm_mma<64, false><<<dim3(1, T / 128, Bb * NH), 256, SMF64>>>(
        sc, v, ao, T, T, Dm, Dm, NH,
        (long long)NH * T * T, (long long)T * T,
        (long long)T * Dm, (long long)HD,
        (long long)T * Dm, (long long)HD,
        nullptr, nullptr, nullptr, 0, 0, 1, 1);

    // 6. out-proj + bo + residual(x)  (exact fp32 output)
    gemm_mma<128, true><<<dim3(Dm / 128, MTOK / 128, 1), 256, SMT128>>>(
        ao, wo, at, Dm, Dm, Dm, Dm, 1, Z, Z, Z, Z, Z, Z, bo, x, nullptr, 0, 0, 0, 0);

    // 7. LayerNorm (rounded output)
    layernorm_k<<<MTOK, 256>>>(at, lng, lnb, ln);

    // 8. FFN1 + ReLU (rounded output)
    gemm_mma<128, false><<<dim3(FF / 128, MTOK / 128, 1), 256, SMF128>>>(
        ln, w1, h1, Dm, Dm, FF, FF, 1, Z, Z, Z, Z, Z, Z, b1, nullptr, nullptr, 1, 0, 0, 1);

    // 9. FFN2 + b2 + residual(at) -> out (exact fp32 output)
    gemm_mma<128, false><<<dim3(Dm / 128, MTOK / 128, 1), 256, SMF128>>>(
        h1, w2, out, FF, FF, Dm, Dm, 1, Z, Z, Z, Z, Z, Z, b2, at, nullptr, 0, 0, 0, 0);
}

// round 13
// speedup vs baseline: 1.1037x; 1.0415x over previous
#include <cuda_runtime.h>
#include <math.h>
#include <stdint.h>

// Problem constants
constexpr int Bb   = 8;
constexpr int T    = 1024;
constexpr int Dm   = 1024;
constexpr int NH   = 16;
constexpr int HD   = 64;
constexpr int FF   = 4096;
constexpr int MTOK = Bb * T;            // 8192 tokens

// ----------------------------------------------------------------------------
// Scratch (allocation-free: __device__ globals)
// ----------------------------------------------------------------------------
__device__ __align__(256) float g_xn[(size_t)MTOK * Dm];
__device__ __align__(256) float g_q [(size_t)MTOK * Dm];
__device__ __align__(256) float g_k [(size_t)MTOK * Dm];
__device__ __align__(256) float g_v [(size_t)MTOK * Dm];
__device__ __align__(256) float g_sc[(size_t)Bb * NH * T * T];   // 512 MB scores
__device__ __align__(256) float g_ao[(size_t)MTOK * Dm];
__device__ __align__(256) float g_at[(size_t)MTOK * Dm];
__device__ __align__(256) float g_ln[(size_t)MTOK * Dm];
__device__ __align__(256) float g_h1[(size_t)MTOK * FF];

// ----------------------------------------------------------------------------
// Baseline-PTX helpers (no 'a'-gated instructions — harness compiles compute_103)
// ----------------------------------------------------------------------------
__device__ __forceinline__ uint32_t smem_u32(const void* p) {
    uint32_t a;
    asm("{ .reg .u64 t; cvta.to.shared.u64 t, %1; cvt.u32.u64 %0, t; }" : "=r"(a) : "l"(p));
    return a;
}
__device__ __forceinline__ void cpa16(void* dst, const void* src) {
    uint32_t d = smem_u32(dst);
    asm volatile("cp.async.cg.shared.global [%0], [%1], 16;" :: "r"(d), "l"(src) : "memory");
}
// Activations are pre-rounded to tf32 (RNA) by producers, so raw-bit
// truncation here is lossless for them; weights take one-sided truncation.
__device__ __forceinline__ uint32_t f2tf(float f) {
    return __float_as_uint(f);
}
// RNA tf32 rounding (producer epilogues only — never in the GEMM inner loop)
__device__ __forceinline__ float rndtf(float f) {
    uint32_t u;
    asm("cvt.rna.tf32.f32 %0, %1;" : "=r"(u) : "f"(f));
    return __uint_as_float(u);
}
__device__ __forceinline__ void mma8(float* c, const uint32_t* a, uint32_t b0, uint32_t b1) {
    asm volatile(
        "mma.sync.aligned.m16n8k8.row.col.f32.tf32.tf32.f32 "
        "{%0,%1,%2,%3}, {%4,%5,%6,%7}, {%8,%9}, {%0,%1,%2,%3};"
        : "+f"(c[0]), "+f"(c[1]), "+f"(c[2]), "+f"(c[3])
        : "r"(a[0]), "r"(a[1]), "r"(a[2]), "r"(a[3]), "r"(b0), "r"(b1));
}
// ldmatrix on f32 data: each 8x8 b16 matrix = 8x4 f32 chunk (16B rows);
// lane l receives f32 element [row l/4][col l%4] — exactly the tf32 mma
// fragment distribution. x4 = full m16k8 A fragment; x2 = m8k8 B fragment.
__device__ __forceinline__ void ldm4(uint32_t* r, uint32_t addr) {
    asm volatile("ldmatrix.sync.aligned.m8n8.x4.shared.b16 {%0,%1,%2,%3}, [%4];"
                 : "=r"(r[0]), "=r"(r[1]), "=r"(r[2]), "=r"(r[3]) : "r"(addr));
}
__device__ __forceinline__ void ldm2(uint32_t* r, uint32_t addr) {
    asm volatile("ldmatrix.sync.aligned.m8n8.x2.shared.b16 {%0,%1}, [%2];"
                 : "=r"(r[0]), "=r"(r[1]) : "r"(addr));
}

// ----------------------------------------------------------------------------
// Tensor-core (mma.sync tf32) GEMM — 3-stage cp.async pipeline, ONE sync/slab:
// 128xBN CTA, 256 threads, 8 warps of 32x64, K slab 32, 2 CTAs/SM.
// A row-major [m][k]. B: TB=false -> B[k][n]; TB=true -> B[n][k].
// Two-level batch z -> (z/zdiv, z%zdiv) with elementwise strides.
// Epilogue: +bias[n], *softplus-q-scale(n&63), ReLU, +resid, tf32-round (rnd).
// causal:   skip C tiles fully above the diagonal (scores GEMM).
// causalK:  clamp K loop to m0+BM (PV GEMM; P is exactly 0 for s > t).
// Safety of single sync: at iteration s the sync orders all warps after
// compute(s-1); buffer (s+2)%3 == (s-1)%3 is then dead and safe to refill.
// ----------------------------------------------------------------------------
constexpr int BM = 128;
constexpr int BK = 32;
constexpr int NSTG = 3;

template <int BN, bool TB>
__global__ void __launch_bounds__(256, 2) gemm_mma(
    const float* __restrict__ A, const float* __restrict__ B, float* __restrict__ C,
    int K, int lda, int ldb, int ldc, int zdiv,
    long long sA1, long long sA2, long long sB1, long long sB2,
    long long sC1, long long sC2,
    const float* __restrict__ bias, const float* __restrict__ resid,
    const float* __restrict__ pds, int relu, int causal, int causalK, int rnd)
{
    constexpr int AW = BK + 4;                 // A row words (stride 144B: conflict-free ldmatrix)
    constexpr int BW = TB ? (BK + 4) : (BN + 8);
    constexpr int AS = BM * AW;
    constexpr int BS = TB ? BN * BW : BK * BW;
    constexpr int STW = AS + BS;               // words per stage
    constexpr int NT = BN / 16;                // n-subtiles per warp (warp covers BN/2 cols)
    extern __shared__ float sm[];

    int m0 = blockIdx.y * BM;
    int n0 = blockIdx.x * BN;
    if (causal && n0 > m0 + BM - 1) return;

    int z = blockIdx.z, z1 = z / zdiv, z2 = z - z1 * zdiv;
    A += z1 * sA1 + z2 * sA2;
    B += z1 * sB1 + z2 * sB2;
    long long oC = z1 * sC1 + z2 * sC2;

    int tid  = threadIdx.x;
    int lane = tid & 31;
    int w    = tid >> 5;
    int g    = lane >> 2, tg = lane & 3;
    int wm   = (w & 3) * 32;            // warp row offset in tile
    int wn   = (w >> 2) * (BN / 2);     // warp col offset in tile

    float acc[2][NT][4];
    #pragma unroll
    for (int mt = 0; mt < 2; mt++)
        #pragma unroll
        for (int nt = 0; nt < NT; nt++)
            #pragma unroll
            for (int i = 0; i < 4; i++) acc[mt][nt][i] = 0.f;

    int Keff = K;
    if (causalK && m0 + BM < K) Keff = m0 + BM;   // P[t][s] == 0 for s > t
    int nslab = Keff / BK;

    // ldmatrix lane base offsets (bytes) within a stage
    uint32_t smBase = smem_u32(sm);
    uint32_t aOff = (uint32_t)((wm + (lane & 15)) * AW + (lane >> 4) * 4) * 4;
    uint32_t bOff = (uint32_t)((wn + (lane & 7)) * BW + ((lane >> 3) & 1) * 4) * 4;

    auto loadSlab = [&](int buf, int slab) {
        float* As = sm + buf * STW;
        float* Bs = As + AS;
        int ko = slab * BK;
        #pragma unroll
        for (int i = 0; i < (BM * 8) / 256; i++) {           // A: 128 x 8 float4
            int c = tid + i * 256;
            int r = c >> 3, f = (c & 7) * 4;
            cpa16(&As[r * AW + f], A + (long long)(m0 + r) * lda + ko + f);
        }
        if (TB) {
            #pragma unroll
            for (int i = 0; i < (BN * 8) / 256; i++) {       // B: BN x 8 float4
                int c = tid + i * 256;
                int r = c >> 3, f = (c & 7) * 4;
                cpa16(&Bs[r * BW + f], B + (long long)(n0 + r) * ldb + ko + f);
            }
        } else {
            #pragma unroll
            for (int i = 0; i < (BK * (BN / 4)) / 256; i++) { // B: 32 x (BN/4) float4
                int c = tid + i * 256;
                int r = c / (BN / 4), f = (c % (BN / 4)) * 4;
                cpa16(&Bs[r * BW + f], B + (long long)(ko + r) * ldb + n0 + f);
            }
        }
        asm volatile("cp.async.commit_group;" ::: "memory");
    };

    auto compute = [&](int buf) {
        uint32_t stBase = smBase + (uint32_t)(buf * STW) * 4;
        uint32_t aB = stBase + aOff;
        uint32_t bB = stBase + (uint32_t)AS * 4 + bOff;
        const float* Bs = sm + buf * STW + AS;
        #pragma unroll
        for (int kk = 0; kk < 4; kk++) {
            int k = kk * 8;
            uint32_t af[2][4];
            ldm4(af[0], aB + k * 4);                    // rows wm..wm+15
            ldm4(af[1], aB + 16 * AW * 4 + k * 4);      // rows wm+16..wm+31
            #pragma unroll
            for (int nt = 0; nt < NT; nt++) {
                uint32_t b[2];
                if (TB) {
                    ldm2(b, bB + nt * 8 * BW * 4 + k * 4);
                } else {
                    int cn = wn + nt * 8 + g;
                    b[0] = f2tf(Bs[(k + tg) * BW + cn]);
                    b[1] = f2tf(Bs[(k + tg + 4) * BW + cn]);
                }
                mma8(acc[0][nt], af[0], b[0], b[1]);
                mma8(acc[1][nt], af[1], b[0], b[1]);
            }
        }
    };

    // Prologue: fill first two stages
    loadSlab(0, 0);
    if (nslab > 1) loadSlab(1, 1);

    for (int s = 0; s < nslab; s++) {
        if (s + 1 < nslab) {
            asm volatile("cp.async.wait_group 1;" ::: "memory");
        } else {
            asm volatile("cp.async.wait_group 0;" ::: "memory");
        }
        __syncthreads();                       // single barrier per slab
        if (s + 2 < nslab) loadSlab((s + 2) % NSTG, s + 2);
        compute(s % NSTG);
    }

    // Epilogue
    float* Cb = C + oC;
    const float* Rb = resid ? resid + oC : nullptr;
    #pragma unroll
    for (int mt = 0; mt < 2; mt++) {
        #pragma unroll
        for (int nt = 0; nt < NT; nt++) {
            int cn = n0 + wn + nt * 8 + 2 * tg;
            float bv0 = 0.f, bv1 = 0.f, s0 = 1.f, s1 = 1.f;
            if (bias) { bv0 = bias[cn]; bv1 = bias[cn + 1]; }
            if (pds) {
                float p0 = pds[cn & (HD - 1)], p1 = pds[(cn + 1) & (HD - 1)];
                float sp0 = (p0 > 20.f) ? p0 : log1pf(expf(p0));
                float sp1 = (p1 > 20.f) ? p1 : log1pf(expf(p1));
                s0 = 0.1803368801111f * sp0;   // log2(e)/sqrt(64) * softplus
                s1 = 0.1803368801111f * sp1;
            }
            #pragma unroll
            for (int h = 0; h < 2; h++) {
                int r = m0 + wm + mt * 16 + g + h * 8;
                float v0 = acc[mt][nt][h * 2 + 0];
                float v1 = acc[mt][nt][h * 2 + 1];
                if (bias) { v0 += bv0; v1 += bv1; }
                if (pds)  { v0 *= s0; v1 *= s1; }
                if (relu) { v0 = fmaxf(v0, 0.f); v1 = fmaxf(v1, 0.f); }
                long long off = (long long)r * ldc + cn;
                if (Rb) {
                    float2 rr = *reinterpret_cast<const float2*>(Rb + off);
                    v0 += rr.x; v1 += rr.y;
                }
                if (rnd) { v0 = rndtf(v0); v1 = rndtf(v1); }
                *reinterpret_cast<float2*>(Cb + off) = make_float2(v0, v1);
            }
        }
    }
}

// ----------------------------------------------------------------------------
// Elementwise kernels
// ----------------------------------------------------------------------------
__device__ __forceinline__ float warpSum(float v) {
    #pragma unroll
    for (int o = 16; o > 0; o >>= 1) v += __shfl_xor_sync(0xffffffffu, v, o);
    return v;
}
__device__ __forceinline__ float warpMax(float v) {
    #pragma unroll
    for (int o = 16; o > 0; o >>= 1) v = fmaxf(v, __shfl_xor_sync(0xffffffffu, v, o));
    return v;
}

__global__ void __launch_bounds__(256) rmsnorm_k(const float* __restrict__ x,
                                                 const float* __restrict__ g,
                                                 float* __restrict__ out) {
    size_t base = (size_t)blockIdx.x * Dm;
    int tid = threadIdx.x;
    float4 xv = reinterpret_cast<const float4*>(x + base)[tid];
    float ss = xv.x * xv.x + xv.y * xv.y + xv.z * xv.z + xv.w * xv.w;
    __shared__ float sh[8];
    __shared__ float bval;
    ss = warpSum(ss);
    if ((tid & 31) == 0) sh[tid >> 5] = ss;
    __syncthreads();
    if (tid == 0) {
        float s = 0.f;
        #pragma unroll
        for (int i = 0; i < 8; i++) s += sh[i];
        bval = s;
    }
    __syncthreads();
    float r = rsqrtf(bval * (1.0f / Dm) + 1e-6f);
    float4 gv = reinterpret_cast<const float4*>(g)[tid];
    reinterpret_cast<float4*>(out + base)[tid] =
        make_float4(rndtf(xv.x * r * gv.x), rndtf(xv.y * r * gv.y),
                    rndtf(xv.z * r * gv.z), rndtf(xv.w * r * gv.w));
}

__global__ void __launch_bounds__(256) layernorm_k(const float* __restrict__ x,
                                                   const float* __restrict__ gamma,
                                                   const float* __restrict__ beta,
                                                   float* __restrict__ out) {
    size_t base = (size_t)blockIdx.x * Dm;
    int tid = threadIdx.x;
    float4 xv = reinterpret_cast<const float4*>(x + base)[tid];
    float s1 = xv.x + xv.y + xv.z + xv.w;
    float s2 = xv.x * xv.x + xv.y * xv.y + xv.z * xv.z + xv.w * xv.w;
    __shared__ float shA[8], shB[8];
    __shared__ float bm, bv2;
    s1 = warpSum(s1);
    s2 = warpSum(s2);
    if ((tid & 31) == 0) { shA[tid >> 5] = s1; shB[tid >> 5] = s2; }
    __syncthreads();
    if (tid == 0) {
        float a = 0.f, b = 0.f;
        #pragma unroll
        for (int i = 0; i < 8; i++) { a += shA[i]; b += shB[i]; }
        bm = a * (1.0f / Dm); bv2 = b * (1.0f / Dm);
    }
    __syncthreads();
    float mean = bm;
    float r = rsqrtf(bv2 - mean * mean + 1e-5f);
    float4 gv = reinterpret_cast<const float4*>(gamma)[tid];
    float4 bvv = reinterpret_cast<const float4*>(beta)[tid];
    reinterpret_cast<float4*>(out + base)[tid] =
        make_float4(rndtf((xv.x - mean) * r * gv.x + bvv.x),
                    rndtf((xv.y - mean) * r * gv.y + bvv.y),
                    rndtf((xv.z - mean) * r * gv.z + bvv.z),
                    rndtf((xv.w - mean) * r * gv.w + bvv.w));
}

// Masked softmax, causal-limited: only s < L = roundup128(t+1) is ever read
// downstream (PV clamps K to the diagonal tile), and scores beyond L were
// never written by the causal-skipped scores GEMM. Output rounded to tf32.
__global__ void __launch_bounds__(256) softmax_k(float* __restrict__ sc,
                                                 const float* __restrict__ padding) {
    int t = blockIdx.x;
    int z = blockIdx.y;
    int b = z >> 4;
    int L = ((t >> 7) + 1) << 7;              // tile-rounded causal length
    float* row = sc + ((size_t)z * T + t) * T;
    int tid = threadIdx.x;
    int s0 = tid * 4;
    bool act = s0 < L;

    float vals[4] = {-1e9f, -1e9f, -1e9f, -1e9f};
    if (act) {
        float4 rv = reinterpret_cast<float4*>(row)[tid];
        float4 pv = reinterpret_cast<const float4*>(padding + (size_t)b * T)[tid];
        float padt = padding[(size_t)b * T + t];
        float vv[4] = {rv.x, rv.y, rv.z, rv.w};
        float pp[4] = {pv.x, pv.y, pv.z, pv.w};
        #pragma unroll
        for (int i = 0; i < 4; i++) {
            bool ok = (s0 + i <= t) && (padt != 0.f) && (pp[i] != 0.f);
            vals[i] = ok ? vv[i] : -1e9f;
        }
    }
    float mx = fmaxf(fmaxf(vals[0], vals[1]), fmaxf(vals[2], vals[3]));

    __shared__ float sh[8];
    __shared__ float bmax, bsum;
    mx = warpMax(mx);
    if ((tid & 31) == 0) sh[tid >> 5] = mx;
    __syncthreads();
    if (tid == 0) {
        float m = sh[0];
        #pragma unroll
        for (int i = 1; i < 8; i++) m = fmaxf(m, sh[i]);
        bmax = m;
    }
    __syncthreads();
    mx = bmax;
    float e[4], ls = 0.f;
    #pragma unroll
    for (int i = 0; i < 4; i++) { e[i] = __expf(vals[i] - mx); ls += e[i]; }
    ls = warpSum(ls);
    if ((tid & 31) == 0) sh[tid >> 5] = ls;
    __syncthreads();
    if (tid == 0) {
        float s = 0.f;
        #pragma unroll
        for (int i = 0; i < 8; i++) s += sh[i];
        bsum = s;
    }
    __syncthreads();
    float inv = 1.0f / bsum;
    if (act) {
        reinterpret_cast<float4*>(row)[tid] =
            make_float4(rndtf(e[0] * inv), rndtf(e[1] * inv),
                        rndtf(e[2] * inv), rndtf(e[3] * inv));
    }
}

// ----------------------------------------------------------------------------
// Launch
// ----------------------------------------------------------------------------
extern "C" void kernel_launch(void* const* d_in, const int* in_sizes, int n_in,
                              void* d_out, int out_size) {
    const float* x    = (const float*)d_in[0];
    const float* pad  = (const float*)d_in[1];
    const float* rmss = (const float*)d_in[2];
    const float* pds  = (const float*)d_in[3];
    const float* wq   = (const float*)d_in[4];
    const float* bq   = (const float*)d_in[5];
    const float* wk   = (const float*)d_in[6];
    const float* bk   = (const float*)d_in[7];
    const float* wv   = (const float*)d_in[8];
    const float* bv   = (const float*)d_in[9];
    const float* wo   = (const float*)d_in[10];
    const float* bo   = (const float*)d_in[11];
    const float* lng  = (const float*)d_in[12];
    const float* lnb  = (const float*)d_in[13];
    const float* w1   = (const float*)d_in[14];
    const float* b1   = (const float*)d_in[15];
    const float* w2   = (const float*)d_in[16];
    const float* b2   = (const float*)d_in[17];
    float* out = (float*)d_out;

    float *xn, *q, *k, *v, *sc, *ao, *at, *ln, *h1;
    cudaGetSymbolAddress((void**)&xn, g_xn);
    cudaGetSymbolAddress((void**)&q,  g_q);
    cudaGetSymbolAddress((void**)&k,  g_k);
    cudaGetSymbolAddress((void**)&v,  g_v);
    cudaGetSymbolAddress((void**)&sc, g_sc);
    cudaGetSymbolAddress((void**)&ao, g_ao);
    cudaGetSymbolAddress((void**)&at, g_at);
    cudaGetSymbolAddress((void**)&ln, g_ln);
    cudaGetSymbolAddress((void**)&h1, g_h1);

    // Dynamic smem sizes (bytes) per instantiation (3 stages)
    const int SMF128 = (BM * 36 + BK * 136) * NSTG * 4;   // <128,false> : 107520
    const int SMT128 = (BM * 36 + 128 * 36) * NSTG * 4;   // <128,true>  : 110592
    const int SMF64  = (BM * 36 + BK * 72) * NSTG * 4;    // <64,false>  : 82944
    cudaFuncSetAttribute(gemm_mma<128, false>, cudaFuncAttributeMaxDynamicSharedMemorySize, SMF128);
    cudaFuncSetAttribute(gemm_mma<128, true>,  cudaFuncAttributeMaxDynamicSharedMemorySize, SMT128);
    cudaFuncSetAttribute(gemm_mma<64,  false>, cudaFuncAttributeMaxDynamicSharedMemorySize, SMF64);

    const long long Z = 0;

    // 1. RMSNorm (tf32-rounded output)
    rmsnorm_k<<<MTOK, 256>>>(x, rmss, xn);

    // 2. Q/K/V projections (rounded outputs; Q fuses bias + softplus scale)
    gemm_mma<128, false><<<dim3(Dm / 128, MTOK / 128, 1), 256, SMF128>>>(
        xn, wq, q, Dm, Dm, Dm, Dm, 1, Z, Z, Z, Z, Z, Z, bq, nullptr, pds, 0, 0, 0, 1);
    gemm_mma<128, false><<<dim3(Dm / 128, MTOK / 128, 1), 256, SMF128>>>(
        xn, wk, k, Dm, Dm, Dm, Dm, 1, Z, Z, Z, Z, Z, Z, bk, nullptr, nullptr, 0, 0, 0, 1);
    gemm_mma<128, false><<<dim3(Dm / 128, MTOK / 128, 1), 256, SMF128>>>(
        xn, wv, v, Dm, Dm, Dm, Dm, 1, Z, Z, Z, Z, Z, Z, bv, nullptr, nullptr, 0, 0, 0, 1);

    // 3. scores[b,n,t,s] = Q K^T (batched over b,n; causal tile skip)
    gemm_mma<128, true><<<dim3(T / 128, T / 128, Bb * NH), 256, SMT128>>>(
        q, k, sc, HD, Dm, Dm, T, NH,
        (long long)T * Dm, (long long)HD,
        (long long)T * Dm, (long long)HD,
        (long long)NH * T * T, (long long)T * T,
        nullptr, nullptr, nullptr, 0, 1, 0, 0);

    // 4. masked softmax (causal-limited, rounded output)
    softmax_k<<<dim3(T, Bb * NH), 256>>>(sc, pad);

    // 5. attn_out[b,t,n,h] = P V (K clamped to diagonal; rounded output)
    gemm_mma<64, false><<<dim3(1, T / 128, Bb * NH), 256, SMF64>>>(
        sc, v, ao, T, T, Dm, Dm, NH,
        (long long)NH * T * T, (long long)T * T,
        (long long)T * Dm, (long long)HD,
        (long long)T * Dm, (long long)HD,
        nullptr, nullptr, nullptr, 0, 0, 1, 1);

    // 6. out-proj + bo + residual(x)  (exact fp32 output)
    gemm_mma<128, true><<<dim3(Dm / 128, MTOK / 128, 1), 256, SMT128>>>(
        ao, wo, at, Dm, Dm, Dm, Dm, 1, Z, Z, Z, Z, Z, Z, bo, x, nullptr, 0, 0, 0, 0);

    // 7. LayerNorm (rounded output)
    layernorm_k<<<MTOK, 256>>>(at, lng, lnb, ln);

    // 8. FFN1 + ReLU (rounded output)
    gemm_mma<128, false><<<dim3(FF / 128, MTOK / 128, 1), 256, SMF128>>>(
        ln, w1, h1, Dm, Dm, FF, FF, 1, Z, Z, Z, Z, Z, Z, b1, nullptr, nullptr, 1, 0, 0, 1);

    // 9. FFN2 + b2 + residual(at) -> out (exact fp32 output)
    gemm_mma<128, false><<<dim3(Dm / 128, MTOK / 128, 1), 256, SMF128>>>(
        h1, w2, out, FF, FF, Dm, Dm, 1, Z, Z, Z, Z, Z, Z, b2, at, nullptr, 0, 0, 0, 0);
}

// round 14
// speedup vs baseline: 1.6617x; 1.5055x over previous
#include <cuda_runtime.h>
#include <cuda_fp16.h>
#include <math.h>
#include <stdint.h>

// Problem constants
constexpr int Bb   = 8;
constexpr int T    = 1024;
constexpr int Dm   = 1024;
constexpr int NH   = 16;
constexpr int HD   = 64;
constexpr int FF   = 4096;
constexpr int MTOK = Bb * T;            // 8192 tokens

// ----------------------------------------------------------------------------
// Scratch (allocation-free: __device__ globals). Activations + weights in fp16.
// ----------------------------------------------------------------------------
__device__ __align__(256) __half g_xn[(size_t)MTOK * Dm];
__device__ __align__(256) __half g_q [(size_t)MTOK * Dm];
__device__ __align__(256) __half g_k [(size_t)MTOK * Dm];
__device__ __align__(256) __half g_v [(size_t)MTOK * Dm];
__device__ __align__(256) __half g_sc[(size_t)Bb * NH * T * T];   // 256 MB scores
__device__ __align__(256) __half g_ao[(size_t)MTOK * Dm];
__device__ __align__(256) float  g_at[(size_t)MTOK * Dm];
__device__ __align__(256) __half g_ln[(size_t)MTOK * Dm];
__device__ __align__(256) __half g_h1[(size_t)MTOK * FF];
__device__ __align__(256) __half g_wq16[(size_t)Dm * Dm];
__device__ __align__(256) __half g_wk16[(size_t)Dm * Dm];
__device__ __align__(256) __half g_wv16[(size_t)Dm * Dm];
__device__ __align__(256) __half g_wo16[(size_t)Dm * Dm];
__device__ __align__(256) __half g_w116[(size_t)Dm * FF];
__device__ __align__(256) __half g_w216[(size_t)FF * Dm];

// ----------------------------------------------------------------------------
// Baseline-PTX helpers (no 'a'-gated instructions — harness compiles compute_103)
// ----------------------------------------------------------------------------
__device__ __forceinline__ uint32_t smem_u32(const void* p) {
    uint32_t a;
    asm("{ .reg .u64 t; cvta.to.shared.u64 t, %1; cvt.u32.u64 %0, t; }" : "=r"(a) : "l"(p));
    return a;
}
__device__ __forceinline__ void cpa16(void* dst, const void* src) {
    uint32_t d = smem_u32(dst);
    asm volatile("cp.async.cg.shared.global [%0], [%1], 16;" :: "r"(d), "l"(src) : "memory");
}
__device__ __forceinline__ void mma16(float* c, const uint32_t* a, const uint32_t* b) {
    asm volatile(
        "mma.sync.aligned.m16n8k16.row.col.f32.f16.f16.f32 "
        "{%0,%1,%2,%3}, {%4,%5,%6,%7}, {%8,%9}, {%0,%1,%2,%3};"
        : "+f"(c[0]), "+f"(c[1]), "+f"(c[2]), "+f"(c[3])
        : "r"(a[0]), "r"(a[1]), "r"(a[2]), "r"(a[3]), "r"(b[0]), "r"(b[1]));
}
__device__ __forceinline__ void ldm4(uint32_t* r, uint32_t addr) {
    asm volatile("ldmatrix.sync.aligned.m8n8.x4.shared.b16 {%0,%1,%2,%3}, [%4];"
                 : "=r"(r[0]), "=r"(r[1]), "=r"(r[2]), "=r"(r[3]) : "r"(addr));
}
__device__ __forceinline__ void ldm2(uint32_t* r, uint32_t addr) {
    asm volatile("ldmatrix.sync.aligned.m8n8.x2.shared.b16 {%0,%1}, [%2];"
                 : "=r"(r[0]), "=r"(r[1]) : "r"(addr));
}
__device__ __forceinline__ void ldm2t(uint32_t* r, uint32_t addr) {
    asm volatile("ldmatrix.sync.aligned.m8n8.x2.trans.shared.b16 {%0,%1}, [%2];"
                 : "=r"(r[0]), "=r"(r[1]) : "r"(addr));
}

// ----------------------------------------------------------------------------
// fp16 tensor-core GEMM — 128xBN CTA, 256 thr (8 warps of 32x64), K slab 32,
// 3-stage cp.async pipeline (one sync/slab), 2 CTAs/SM, all-ldmatrix loads.
// A fp16 row-major [m][k]. B fp16: TB=false -> B[k][n]; TB=true -> B[n][k].
// Epilogue fp32: +bias, *softplus-q-scale, ReLU, +resid(float out only);
// HOUT=true writes __half (rounding = fp16 convert), else float.
// causal:  skip C tiles above diagonal. causalK: clamp K to m0+BM (PV).
// ----------------------------------------------------------------------------
constexpr int BM = 128;
constexpr int BK = 32;
constexpr int NSTG = 3;

template <int BN, bool TB, bool HOUT>
__global__ void __launch_bounds__(256, 2) gemm_h(
    const __half* __restrict__ A, const __half* __restrict__ B, void* __restrict__ Cv,
    int K, int lda, int ldb, int ldc, int zdiv,
    long long sA1, long long sA2, long long sB1, long long sB2,
    long long sC1, long long sC2,
    const float* __restrict__ bias, const float* __restrict__ resid,
    const float* __restrict__ pds, int relu, int causal, int causalK)
{
    constexpr int AWh = BK + 8;                // A row halves (80B stride, conflict-free)
    constexpr int BWh = TB ? (BK + 8) : (BN + 8);
    constexpr int ASh = BM * AWh;
    constexpr int BSh = TB ? BN * BWh : BK * BWh;
    constexpr int STWh = ASh + BSh;            // halves per stage
    constexpr int NT = BN / 16;                // n-subtiles per warp (warp covers BN/2 cols)
    constexpr int AWB = AWh * 2;               // byte strides
    constexpr int BWB = BWh * 2;
    extern __shared__ __half smh[];

    int m0 = blockIdx.y * BM;
    int n0 = blockIdx.x * BN;
    if (causal && n0 > m0 + BM - 1) return;

    int z = blockIdx.z, z1 = z / zdiv, z2 = z - z1 * zdiv;
    A += z1 * sA1 + z2 * sA2;
    B += z1 * sB1 + z2 * sB2;
    long long oC = z1 * sC1 + z2 * sC2;

    int tid  = threadIdx.x;
    int lane = tid & 31;
    int w    = tid >> 5;
    int g    = lane >> 2, tg = lane & 3;
    int l8   = lane & 15;
    int wm   = (w & 3) * 32;            // warp row offset in tile
    int wn   = (w >> 2) * (BN / 2);     // warp col offset in tile

    float acc[2][NT][4];
    #pragma unroll
    for (int mt = 0; mt < 2; mt++)
        #pragma unroll
        for (int nt = 0; nt < NT; nt++)
            #pragma unroll
            for (int i = 0; i < 4; i++) acc[mt][nt][i] = 0.f;

    int Keff = K;
    if (causalK && m0 + BM < K) Keff = m0 + BM;   // P[t][s] == 0 for s > t
    int nslab = Keff / BK;

    uint32_t smBase = smem_u32(smh);
    // A ldmatrix lane address: rows wm+(l&15), k-half select by lane>>4
    uint32_t aOff = (uint32_t)((wm + l8) * AWB + (lane >> 4) * 16);
    // B lane address (x2 uses lanes 0-15; replicate for 16-31)
    uint32_t bOff = TB ? (uint32_t)((wn + (l8 & 7)) * BWB + (l8 >> 3) * 16)
                       : (uint32_t)(l8 * BWB + wn * 2);

    auto loadSlab = [&](int buf, int slab) {
        __half* As = smh + buf * STWh;
        __half* Bs = As + ASh;
        int ko = slab * BK;
        #pragma unroll
        for (int i = 0; i < (BM * 4) / 256; i++) {           // A: 128 rows x 4 chunks
            int c = tid + i * 256;
            int r = c >> 2, f = (c & 3) * 8;
            cpa16(&As[r * AWh + f], A + (long long)(m0 + r) * lda + ko + f);
        }
        if (TB) {
            #pragma unroll
            for (int i = 0; i < (BN * 4) / 256; i++) {       // B: BN rows x 4 chunks
                int c = tid + i * 256;
                int r = c >> 2, f = (c & 3) * 8;
                cpa16(&Bs[r * BWh + f], B + (long long)(n0 + r) * ldb + ko + f);
            }
        } else {
            #pragma unroll
            for (int i = 0; i < (BK * (BN / 8)) / 256; i++) { // B: 32 rows x BN/8 chunks
                int c = tid + i * 256;
                int r = c / (BN / 8), f = (c % (BN / 8)) * 8;
                cpa16(&Bs[r * BWh + f], B + (long long)(ko + r) * ldb + n0 + f);
            }
        }
        asm volatile("cp.async.commit_group;" ::: "memory");
    };

    auto compute = [&](int buf) {
        uint32_t stBase = smBase + (uint32_t)(buf * STWh) * 2;
        uint32_t aB = stBase + aOff;
        uint32_t bB = stBase + (uint32_t)ASh * 2 + bOff;
        #pragma unroll
        for (int kk = 0; kk < BK / 16; kk++) {
            uint32_t af[2][4];
            ldm4(af[0], aB + kk * 32);                  // rows wm..wm+15
            ldm4(af[1], aB + 16 * AWB + kk * 32);       // rows wm+16..wm+31
            #pragma unroll
            for (int nt = 0; nt < NT; nt++) {
                uint32_t b[2];
                if (TB) ldm2 (b, bB + nt * 8 * BWB + kk * 32);
                else    ldm2t(b, bB + nt * 16 + kk * 16 * BWB);
                mma16(acc[0][nt], af[0], b);
                mma16(acc[1][nt], af[1], b);
            }
        }
    };

    // Prologue: fill first two stages
    loadSlab(0, 0);
    if (nslab > 1) loadSlab(1, 1);

    for (int s = 0; s < nslab; s++) {
        if (s + 1 < nslab) {
            asm volatile("cp.async.wait_group 1;" ::: "memory");
        } else {
            asm volatile("cp.async.wait_group 0;" ::: "memory");
        }
        __syncthreads();                       // single barrier per slab
        if (s + 2 < nslab) loadSlab((s + 2) % NSTG, s + 2);
        compute(s % NSTG);
    }

    // Epilogue (fp32 math)
    const float* Rb = resid ? resid + oC : nullptr;
    #pragma unroll
    for (int mt = 0; mt < 2; mt++) {
        #pragma unroll
        for (int nt = 0; nt < NT; nt++) {
            int cn = n0 + wn + nt * 8 + 2 * tg;
            float bv0 = 0.f, bv1 = 0.f, s0 = 1.f, s1 = 1.f;
            if (bias) { bv0 = bias[cn]; bv1 = bias[cn + 1]; }
            if (pds) {
                float p0 = pds[cn & (HD - 1)], p1 = pds[(cn + 1) & (HD - 1)];
                float sp0 = (p0 > 20.f) ? p0 : log1pf(expf(p0));
                float sp1 = (p1 > 20.f) ? p1 : log1pf(expf(p1));
                s0 = 0.1803368801111f * sp0;   // log2(e)/sqrt(64) * softplus
                s1 = 0.1803368801111f * sp1;
            }
            #pragma unroll
            for (int h = 0; h < 2; h++) {
                int r = m0 + wm + mt * 16 + g + h * 8;
                float v0 = acc[mt][nt][h * 2 + 0];
                float v1 = acc[mt][nt][h * 2 + 1];
                if (bias) { v0 += bv0; v1 += bv1; }
                if (pds)  { v0 *= s0; v1 *= s1; }
                if (relu) { v0 = fmaxf(v0, 0.f); v1 = fmaxf(v1, 0.f); }
                long long off = oC + (long long)r * ldc + cn;
                if (HOUT) {
                    *reinterpret_cast<__half2*>((__half*)Cv + off) =
                        __floats2half2_rn(v0, v1);
                } else {
                    if (Rb) {
                        float2 rr = *reinterpret_cast<const float2*>(
                            resid + off);
                        v0 += rr.x; v1 += rr.y;
                    }
                    *reinterpret_cast<float2*>((float*)Cv + off) =
                        make_float2(v0, v1);
                }
            }
        }
    }
}

// ----------------------------------------------------------------------------
// Elementwise kernels
// ----------------------------------------------------------------------------
__device__ __forceinline__ float warpSum(float v) {
    #pragma unroll
    for (int o = 16; o > 0; o >>= 1) v += __shfl_xor_sync(0xffffffffu, v, o);
    return v;
}
__device__ __forceinline__ float warpMax(float v) {
    #pragma unroll
    for (int o = 16; o > 0; o >>= 1) v = fmaxf(v, __shfl_xor_sync(0xffffffffu, v, o));
    return v;
}

// fp32 -> fp16 weight conversion
__global__ void __launch_bounds__(256) cvt16_k(const float4* __restrict__ in,
                                               __half2* __restrict__ out, int n4) {
    int i = blockIdx.x * 256 + threadIdx.x;
    if (i < n4) {
        float4 v = in[i];
        out[2 * i]     = __floats2half2_rn(v.x, v.y);
        out[2 * i + 1] = __floats2half2_rn(v.z, v.w);
    }
}

__global__ void __launch_bounds__(256) rmsnorm_k(const float* __restrict__ x,
                                                 const float* __restrict__ g,
                                                 __half* __restrict__ out) {
    size_t base = (size_t)blockIdx.x * Dm;
    int tid = threadIdx.x;
    float4 xv = reinterpret_cast<const float4*>(x + base)[tid];
    float ss = xv.x * xv.x + xv.y * xv.y + xv.z * xv.z + xv.w * xv.w;
    __shared__ float sh[8];
    __shared__ float bval;
    ss = warpSum(ss);
    if ((tid & 31) == 0) sh[tid >> 5] = ss;
    __syncthreads();
    if (tid == 0) {
        float s = 0.f;
        #pragma unroll
        for (int i = 0; i < 8; i++) s += sh[i];
        bval = s;
    }
    __syncthreads();
    float r = rsqrtf(bval * (1.0f / Dm) + 1e-6f);
    float4 gv = reinterpret_cast<const float4*>(g)[tid];
    __half2* o2 = reinterpret_cast<__half2*>(out + base);
    o2[tid * 2]     = __floats2half2_rn(xv.x * r * gv.x, xv.y * r * gv.y);
    o2[tid * 2 + 1] = __floats2half2_rn(xv.z * r * gv.z, xv.w * r * gv.w);
}

__global__ void __launch_bounds__(256) layernorm_k(const float* __restrict__ x,
                                                   const float* __restrict__ gamma,
                                                   const float* __restrict__ beta,
                                                   __half* __restrict__ out) {
    size_t base = (size_t)blockIdx.x * Dm;
    int tid = threadIdx.x;
    float4 xv = reinterpret_cast<const float4*>(x + base)[tid];
    float s1 = xv.x + xv.y + xv.z + xv.w;
    float s2 = xv.x * xv.x + xv.y * xv.y + xv.z * xv.z + xv.w * xv.w;
    __shared__ float shA[8], shB[8];
    __shared__ float bm, bv2;
    s1 = warpSum(s1);
    s2 = warpSum(s2);
    if ((tid & 31) == 0) { shA[tid >> 5] = s1; shB[tid >> 5] = s2; }
    __syncthreads();
    if (tid == 0) {
        float a = 0.f, b = 0.f;
        #pragma unroll
        for (int i = 0; i < 8; i++) { a += shA[i]; b += shB[i]; }
        bm = a * (1.0f / Dm); bv2 = b * (1.0f / Dm);
    }
    __syncthreads();
    float mean = bm;
    float r = rsqrtf(bv2 - mean * mean + 1e-5f);
    float4 gv = reinterpret_cast<const float4*>(gamma)[tid];
    float4 bvv = reinterpret_cast<const float4*>(beta)[tid];
    __half2* o2 = reinterpret_cast<__half2*>(out + base);
    o2[tid * 2]     = __floats2half2_rn((xv.x - mean) * r * gv.x + bvv.x,
                                        (xv.y - mean) * r * gv.y + bvv.y);
    o2[tid * 2 + 1] = __floats2half2_rn((xv.z - mean) * r * gv.z + bvv.z,
                                        (xv.w - mean) * r * gv.w + bvv.w);
}

// Masked softmax over fp16 scores, causal-limited (only s < roundup128(t+1)
// is ever read downstream — PV clamps K; scores beyond were never written).
__global__ void __launch_bounds__(256) softmax_k(__half* __restrict__ sc,
                                                 const float* __restrict__ padding) {
    int t = blockIdx.x;
    int z = blockIdx.y;
    int b = z >> 4;
    int L = ((t >> 7) + 1) << 7;              // tile-rounded causal length
    __half* row = sc + ((size_t)z * T + t) * T;
    int tid = threadIdx.x;
    int s0 = tid * 4;
    bool act = s0 < L;

    float vals[4] = {-1e9f, -1e9f, -1e9f, -1e9f};
    if (act) {
        __half2 h0 = reinterpret_cast<const __half2*>(row)[tid * 2];
        __half2 h1 = reinterpret_cast<const __half2*>(row)[tid * 2 + 1];
        float4 pv = reinterpret_cast<const float4*>(padding + (size_t)b * T)[tid];
        float padt = padding[(size_t)b * T + t];
        float vv[4] = {__low2float(h0), __high2float(h0),
                       __low2float(h1), __high2float(h1)};
        float pp[4] = {pv.x, pv.y, pv.z, pv.w};
        #pragma unroll
        for (int i = 0; i < 4; i++) {
            bool ok = (s0 + i <= t) && (padt != 0.f) && (pp[i] != 0.f);
            vals[i] = ok ? vv[i] : -1e9f;
        }
    }
    float mx = fmaxf(fmaxf(vals[0], vals[1]), fmaxf(vals[2], vals[3]));

    __shared__ float sh[8];
    __shared__ float bmax, bsum;
    mx = warpMax(mx);
    if ((tid & 31) == 0) sh[tid >> 5] = mx;
    __syncthreads();
    if (tid == 0) {
        float m = sh[0];
        #pragma unroll
        for (int i = 1; i < 8; i++) m = fmaxf(m, sh[i]);
        bmax = m;
    }
    __syncthreads();
    mx = bmax;
    float e[4], ls = 0.f;
    #pragma unroll
    for (int i = 0; i < 4; i++) { e[i] = __expf(vals[i] - mx); ls += e[i]; }
    ls = warpSum(ls);
    if ((tid & 31) == 0) sh[tid >> 5] = ls;
    __syncthreads();
    if (tid == 0) {
        float s = 0.f;
        #pragma unroll
        for (int i = 0; i < 8; i++) s += sh[i];
        bsum = s;
    }
    __syncthreads();
    float inv = 1.0f / bsum;
    if (act) {
        reinterpret_cast<__half2*>(row)[tid * 2]     =
            __floats2half2_rn(e[0] * inv, e[1] * inv);
        reinterpret_cast<__half2*>(row)[tid * 2 + 1] =
            __floats2half2_rn(e[2] * inv, e[3] * inv);
    }
}

// ----------------------------------------------------------------------------
// Launch
// ----------------------------------------------------------------------------
extern "C" void kernel_launch(void* const* d_in, const int* in_sizes, int n_in,
                              void* d_out, int out_size) {
    const float* x    = (const float*)d_in[0];
    const float* pad  = (const float*)d_in[1];
    const float* rmss = (const float*)d_in[2];
    const float* pds  = (const float*)d_in[3];
    const float* wq   = (const float*)d_in[4];
    const float* bq   = (const float*)d_in[5];
    const float* wk   = (const float*)d_in[6];
    const float* bk   = (const float*)d_in[7];
    const float* wv   = (const float*)d_in[8];
    const float* bv   = (const float*)d_in[9];
    const float* wo   = (const float*)d_in[10];
    const float* bo   = (const float*)d_in[11];
    const float* lng  = (const float*)d_in[12];
    const float* lnb  = (const float*)d_in[13];
    const float* w1   = (const float*)d_in[14];
    const float* b1   = (const float*)d_in[15];
    const float* w2   = (const float*)d_in[16];
    const float* b2   = (const float*)d_in[17];
    float* out = (float*)d_out;

    __half *xn, *q, *k, *v, *sc, *ao, *ln, *h1;
    __half *wq16, *wk16, *wv16, *wo16, *w116, *w216;
    float *at;
    cudaGetSymbolAddress((void**)&xn, g_xn);
    cudaGetSymbolAddress((void**)&q,  g_q);
    cudaGetSymbolAddress((void**)&k,  g_k);
    cudaGetSymbolAddress((void**)&v,  g_v);
    cudaGetSymbolAddress((void**)&sc, g_sc);
    cudaGetSymbolAddress((void**)&ao, g_ao);
    cudaGetSymbolAddress((void**)&at, g_at);
    cudaGetSymbolAddress((void**)&ln, g_ln);
    cudaGetSymbolAddress((void**)&h1, g_h1);
    cudaGetSymbolAddress((void**)&wq16, g_wq16);
    cudaGetSymbolAddress((void**)&wk16, g_wk16);
    cudaGetSymbolAddress((void**)&wv16, g_wv16);
    cudaGetSymbolAddress((void**)&wo16, g_wo16);
    cudaGetSymbolAddress((void**)&w116, g_w116);
    cudaGetSymbolAddress((void**)&w216, g_w216);

    // Dynamic smem (bytes), 3 stages of fp16 tiles
    const int SMF128 = (BM * 40 + BK * 136) * NSTG * 2;   // <128,false> : 56832
    const int SMT128 = (BM * 40 + 128 * 40) * NSTG * 2;   // <128,true>  : 61440
    const int SMF64  = (BM * 40 + BK * 72) * NSTG * 2;    // <64,false>  : 44544
    cudaFuncSetAttribute((const void*)gemm_h<128, false, true>,
                         cudaFuncAttributeMaxDynamicSharedMemorySize, SMF128);
    cudaFuncSetAttribute((const void*)gemm_h<128, false, false>,
                         cudaFuncAttributeMaxDynamicSharedMemorySize, SMF128);
    cudaFuncSetAttribute((const void*)gemm_h<128, true, true>,
                         cudaFuncAttributeMaxDynamicSharedMemorySize, SMT128);
    cudaFuncSetAttribute((const void*)gemm_h<128, true, false>,
                         cudaFuncAttributeMaxDynamicSharedMemorySize, SMT128);
    cudaFuncSetAttribute((const void*)gemm_h<64, false, true>,
                         cudaFuncAttributeMaxDynamicSharedMemorySize, SMF64);

    const long long Z = 0;

    // 0. weight conversions fp32 -> fp16 (~40us total)
    cvt16_k<<<1024, 256>>>((const float4*)wq, (__half2*)wq16, Dm * Dm / 4);
    cvt16_k<<<1024, 256>>>((const float4*)wk, (__half2*)wk16, Dm * Dm / 4);
    cvt16_k<<<1024, 256>>>((const float4*)wv, (__half2*)wv16, Dm * Dm / 4);
    cvt16_k<<<1024, 256>>>((const float4*)wo, (__half2*)wo16, Dm * Dm / 4);
    cvt16_k<<<4096, 256>>>((const float4*)w1, (__half2*)w116, Dm * FF / 4);
    cvt16_k<<<4096, 256>>>((const float4*)w2, (__half2*)w216, FF * Dm / 4);

    // 1. RMSNorm (fp16 output)
    rmsnorm_k<<<MTOK, 256>>>(x, rmss, xn);

    // 2. Q/K/V projections (fp16 outputs; Q fuses bias + softplus scale)
    gemm_h<128, false, true><<<dim3(Dm / 128, MTOK / 128, 1), 256, SMF128>>>(
        xn, wq16, q, Dm, Dm, Dm, Dm, 1, Z, Z, Z, Z, Z, Z, bq, nullptr, pds, 0, 0, 0);
    gemm_h<128, false, true><<<dim3(Dm / 128, MTOK / 128, 1), 256, SMF128>>>(
        xn, wk16, k, Dm, Dm, Dm, Dm, 1, Z, Z, Z, Z, Z, Z, bk, nullptr, nullptr, 0, 0, 0);
    gemm_h<128, false, true><<<dim3(Dm / 128, MTOK / 128, 1), 256, SMF128>>>(
        xn, wv16, v, Dm, Dm, Dm, Dm, 1, Z, Z, Z, Z, Z, Z, bv, nullptr, nullptr, 0, 0, 0);

    // 3. scores[b,n,t,s] = Q K^T (batched over b,n; causal tile skip)
    gemm_h<128, true, true><<<dim3(T / 128, T / 128, Bb * NH), 256, SMT128>>>(
        q, k, sc, HD, Dm, Dm, T, NH,
        (long long)T * Dm, (long long)HD,
        (long long)T * Dm, (long long)HD,
        (long long)NH * T * T, (long long)T * T,
        nullptr, nullptr, nullptr, 0, 1, 0);

    // 4. masked softmax (causal-limited, fp16 in/out)
    softmax_k<<<dim3(T, Bb * NH), 256>>>(sc, pad);

    // 5. attn_out[b,t,n,h] = P V (K clamped to diagonal; fp16 output)
    gemm_h<64, false, true><<<dim3(1, T / 128, Bb * NH), 256, SMF64>>>(
        sc, v, ao, T, T, Dm, Dm, NH,
        (long long)NH * T * T, (long long)T * T,
        (long long)T * Dm, (long long)HD,
        (long long)T * Dm, (long long)HD,
        nullptr, nullptr, nullptr, 0, 0, 1);

    // 6. out-proj + bo + residual(x)  (fp32 output)
    gemm_h<128, true, false><<<dim3(Dm / 128, MTOK / 128, 1), 256, SMT128>>>(
        ao, wo16, at, Dm, Dm, Dm, Dm, 1, Z, Z, Z, Z, Z, Z, bo, x, nullptr, 0, 0, 0);

    // 7. LayerNorm (fp16 output)
    layernorm_k<<<MTOK, 256>>>(at, lng, lnb, ln);

    // 8. FFN1 + ReLU (fp16 output)
    gemm_h<128, false, true><<<dim3(FF / 128, MTOK / 128, 1), 256, SMF128>>>(
        ln, w116, h1, Dm, Dm, FF, FF, 1, Z, Z, Z, Z, Z, Z, b1, nullptr, nullptr, 1, 0, 0);

    // 9. FFN2 + b2 + residual(at) -> out (fp32 output)
    gemm_h<128, false, false><<<dim3(Dm / 128, MTOK / 128, 1), 256, SMF128>>>(
        h1, w216, out, FF, FF, Dm, Dm, 1, Z, Z, Z, Z, Z, Z, b2, at, nullptr, 0, 0, 0);
}